// round 2
// baseline (speedup 1.0000x reference)
#include <cuda_runtime.h>
#include <math.h>

#define EPS 1e-3f

// ---------------- scratch (device globals; no allocation allowed) ----------------
__device__ float g_X[8 * 4096 * 256];        // bn1+elu(inputs)
__device__ float g_theta[8 * 4096 * 128];
__device__ float g_gfull[8 * 4096 * 128];
__device__ float g_phifull[8 * 4096 * 128];
__device__ float g_gpool[8 * 2048 * 128];
__device__ float g_phipool[8 * 2048 * 128];
__device__ float g_Y[8 * 4096 * 128];

__device__ __forceinline__ float elu_f(float v) { return v > 0.f ? v : expm1f(v); }

// ---------------- kernel 1: x = elu(bn1(inputs)) ----------------
// total elements 8*4096*256 = 8388608 -> 2097152 float4, C=256 -> 64 float4/pixel
__global__ void __launch_bounds__(256) k_bn1_elu(
    const float4* __restrict__ in,
    const float* __restrict__ gamma, const float* __restrict__ beta,
    const float* __restrict__ mean, const float* __restrict__ var,
    float4* __restrict__ X)
{
    int i = blockIdx.x * 256 + threadIdx.x;
    int c = (i & 63) * 4;
    float4 v = in[i];
    float4 o;
    o.x = elu_f(fmaf(v.x - mean[c + 0], gamma[c + 0] * rsqrtf(var[c + 0] + EPS), beta[c + 0]));
    o.y = elu_f(fmaf(v.y - mean[c + 1], gamma[c + 1] * rsqrtf(var[c + 1] + EPS), beta[c + 1]));
    o.z = elu_f(fmaf(v.z - mean[c + 2], gamma[c + 2] * rsqrtf(var[c + 2] + EPS), beta[c + 2]));
    o.w = elu_f(fmaf(v.w - mean[c + 3], gamma[c + 3] * rsqrtf(var[c + 3] + EPS), beta[c + 3]));
    X[i] = o;
}

// ---------------- kernel 2: three 1x1 convs as SGEMM [32768,256]x[256,128] ----------------
// blockIdx.y in {0,1,2} selects (W, bias, out) = (theta, g, phi)
__global__ void __launch_bounds__(256) k_gemm3(
    const float* __restrict__ A,
    const float* __restrict__ W0, const float* __restrict__ b0, float* __restrict__ C0,
    const float* __restrict__ W1, const float* __restrict__ b1, float* __restrict__ C1,
    const float* __restrict__ W2, const float* __restrict__ b2, float* __restrict__ C2)
{
    const float* W; const float* bias; float* C;
    if (blockIdx.y == 0)      { W = W0; bias = b0; C = C0; }
    else if (blockIdx.y == 1) { W = W1; bias = b1; C = C1; }
    else                      { W = W2; bias = b2; C = C2; }

    const int K = 256, N = 128;
    int m0 = blockIdx.x * 128;
    __shared__ float As[8][128];
    __shared__ float Bs[8][128];
    int tid = threadIdx.x;
    int ty = tid >> 4, tx = tid & 15;

    float acc[8][8];
#pragma unroll
    for (int i = 0; i < 8; i++)
#pragma unroll
        for (int j = 0; j < 8; j++) acc[i][j] = 0.f;

    for (int k0 = 0; k0 < K; k0 += 8) {
        {
            int r = tid >> 1, kc = (tid & 1) * 4;
            float4 v = *(const float4*)(A + (size_t)(m0 + r) * K + k0 + kc);
            As[kc + 0][r] = v.x; As[kc + 1][r] = v.y; As[kc + 2][r] = v.z; As[kc + 3][r] = v.w;
            int kr = tid >> 5, col = (tid & 31) * 4;
            float4 w = *(const float4*)(W + (size_t)(k0 + kr) * N + col);
            *(float4*)&Bs[kr][col] = w;
        }
        __syncthreads();
#pragma unroll
        for (int kk = 0; kk < 8; ++kk) {
            float a[8], b[8];
            *(float4*)&a[0] = *(const float4*)&As[kk][ty * 8];
            *(float4*)&a[4] = *(const float4*)&As[kk][ty * 8 + 4];
            *(float4*)&b[0] = *(const float4*)&Bs[kk][tx * 8];
            *(float4*)&b[4] = *(const float4*)&Bs[kk][tx * 8 + 4];
#pragma unroll
            for (int i = 0; i < 8; i++)
#pragma unroll
                for (int j = 0; j < 8; j++)
                    acc[i][j] = fmaf(a[i], b[j], acc[i][j]);
        }
        __syncthreads();
    }

#pragma unroll
    for (int i = 0; i < 8; i++) {
        size_t row = (size_t)(m0 + ty * 8 + i);
#pragma unroll
        for (int j = 0; j < 8; j += 4) {
            int col = tx * 8 + j;
            float4 v = make_float4(acc[i][j] + bias[col], acc[i][j + 1] + bias[col + 1],
                                   acc[i][j + 2] + bias[col + 2], acc[i][j + 3] + bias[col + 3]);
            *(float4*)(C + row * 128 + col) = v;
        }
    }
}

// ---------------- kernel 3: width-2 maxpool for g and phi ----------------
// total float4 elems: 8*2048*32 = 524288
__global__ void __launch_bounds__(256) k_pool(
    const float4* __restrict__ gin, const float4* __restrict__ pin,
    float4* __restrict__ gout, float4* __restrict__ pout)
{
    int i = blockIdx.x * 256 + threadIdx.x;
    int c4 = i & 31;
    int q = i >> 5;          // pooled pixel: (b*64+h)*32 + w2
    int bh = q >> 5;
    int w2 = q & 31;
    int p0 = (bh * 64 + w2 * 2) * 32 + c4;
    int p1 = p0 + 32;
    float4 a = gin[p0], b = gin[p1];
    gout[i] = make_float4(fmaxf(a.x, b.x), fmaxf(a.y, b.y), fmaxf(a.z, b.z), fmaxf(a.w, b.w));
    float4 c = pin[p0], d = pin[p1];
    pout[i] = make_float4(fmaxf(c.x, d.x), fmaxf(c.y, d.y), fmaxf(c.z, d.z), fmaxf(c.w, d.w));
}

// ---------------- kernel 4: flash attention ----------------
// per batch: Q=[4096,128], K(phi_pool)=[2048,128], V(g_pool)=[2048,128]
// block = 64 queries, 256 threads (16x16), key tiles of 64, online softmax.
#define ATTN_SMEM_BYTES (28928 * 4)
__global__ void __launch_bounds__(256, 1) k_attn(
    const float* __restrict__ theta, const float* __restrict__ phi,
    const float* __restrict__ g, float* __restrict__ Y)
{
    extern __shared__ float sm[];
    float* Qs = sm;              // [128][64] k-major
    float* Ks = sm + 8192;       // [128][64] k-major
    float* Gs = sm + 16384;      // [64][128] row-major (key, channel)
    float* Ps = sm + 24576;      // [64][68]

    int b = blockIdx.y;
    int qt = blockIdx.x;
    const float* Q = theta + ((size_t)b * 4096 + qt * 64) * 128;
    const float* Kp = phi + (size_t)b * 2048 * 128;
    const float* Gp = g + (size_t)b * 2048 * 128;

    int tid = threadIdx.x;
    int ty = tid >> 4, tx = tid & 15;

    // load Q tile transposed into Qs[k][r]
    for (int i = tid; i < 64 * 32; i += 256) {
        int r = i >> 5, k4 = (i & 31) * 4;
        float4 v = *(const float4*)(Q + r * 128 + k4);
        Qs[(k4 + 0) * 64 + r] = v.x;
        Qs[(k4 + 1) * 64 + r] = v.y;
        Qs[(k4 + 2) * 64 + r] = v.z;
        Qs[(k4 + 3) * 64 + r] = v.w;
    }

    float o[4][8];
#pragma unroll
    for (int i = 0; i < 4; i++)
#pragma unroll
        for (int j = 0; j < 8; j++) o[i][j] = 0.f;
    float m_reg[4] = {-INFINITY, -INFINITY, -INFINITY, -INFINITY};
    float l_reg[4] = {0.f, 0.f, 0.f, 0.f};

    for (int kt = 0; kt < 32; ++kt) {
        const float* Kt = Kp + (size_t)kt * 64 * 128;
        const float* Gt = Gp + (size_t)kt * 64 * 128;
        for (int i = tid; i < 64 * 32; i += 256) {
            int r = i >> 5, k4 = (i & 31) * 4;
            float4 v = *(const float4*)(Kt + r * 128 + k4);
            Ks[(k4 + 0) * 64 + r] = v.x;
            Ks[(k4 + 1) * 64 + r] = v.y;
            Ks[(k4 + 2) * 64 + r] = v.z;
            Ks[(k4 + 3) * 64 + r] = v.w;
            float4 w = *(const float4*)(Gt + r * 128 + k4);
            *(float4*)&Gs[r * 128 + k4] = w;
        }
        __syncthreads();

        // S = Q @ K^T for 4x4 per thread
        float s[4][4];
#pragma unroll
        for (int i = 0; i < 4; i++)
#pragma unroll
            for (int j = 0; j < 4; j++) s[i][j] = 0.f;
#pragma unroll 4
        for (int k = 0; k < 128; ++k) {
            float4 a = *(const float4*)&Qs[k * 64 + ty * 4];
            float4 bb = *(const float4*)&Ks[k * 64 + tx * 4];
            s[0][0] = fmaf(a.x, bb.x, s[0][0]); s[0][1] = fmaf(a.x, bb.y, s[0][1]);
            s[0][2] = fmaf(a.x, bb.z, s[0][2]); s[0][3] = fmaf(a.x, bb.w, s[0][3]);
            s[1][0] = fmaf(a.y, bb.x, s[1][0]); s[1][1] = fmaf(a.y, bb.y, s[1][1]);
            s[1][2] = fmaf(a.y, bb.z, s[1][2]); s[1][3] = fmaf(a.y, bb.w, s[1][3]);
            s[2][0] = fmaf(a.z, bb.x, s[2][0]); s[2][1] = fmaf(a.z, bb.y, s[2][1]);
            s[2][2] = fmaf(a.z, bb.z, s[2][2]); s[2][3] = fmaf(a.z, bb.w, s[2][3]);
            s[3][0] = fmaf(a.w, bb.x, s[3][0]); s[3][1] = fmaf(a.w, bb.y, s[3][1]);
            s[3][2] = fmaf(a.w, bb.z, s[3][2]); s[3][3] = fmaf(a.w, bb.w, s[3][3]);
        }

        // online softmax per row (row owned by half-warp: lanes tx 0..15, same ty)
#pragma unroll
        for (int i = 0; i < 4; i++) {
            int r = ty * 4 + i;
            float tm = fmaxf(fmaxf(s[i][0], s[i][1]), fmaxf(s[i][2], s[i][3]));
            tm = fmaxf(tm, __shfl_xor_sync(0xffffffffu, tm, 8));
            tm = fmaxf(tm, __shfl_xor_sync(0xffffffffu, tm, 4));
            tm = fmaxf(tm, __shfl_xor_sync(0xffffffffu, tm, 2));
            tm = fmaxf(tm, __shfl_xor_sync(0xffffffffu, tm, 1));
            float mnew = fmaxf(m_reg[i], tm);
            float alpha = __expf(m_reg[i] - mnew);
            float rsum = 0.f;
#pragma unroll
            for (int j = 0; j < 4; j++) {
                float p = __expf(s[i][j] - mnew);
                Ps[r * 68 + tx * 4 + j] = p;
                rsum += p;
            }
            rsum += __shfl_xor_sync(0xffffffffu, rsum, 8);
            rsum += __shfl_xor_sync(0xffffffffu, rsum, 4);
            rsum += __shfl_xor_sync(0xffffffffu, rsum, 2);
            rsum += __shfl_xor_sync(0xffffffffu, rsum, 1);
            l_reg[i] = l_reg[i] * alpha + rsum;
            m_reg[i] = mnew;
#pragma unroll
            for (int j = 0; j < 8; j++) o[i][j] *= alpha;
        }
        __syncwarp();

        // O += P @ G   (rows ty*4+i, cols tx*8+j)
#pragma unroll 4
        for (int kk = 0; kk < 64; ++kk) {
            float p0 = Ps[(ty * 4 + 0) * 68 + kk];
            float p1 = Ps[(ty * 4 + 1) * 68 + kk];
            float p2 = Ps[(ty * 4 + 2) * 68 + kk];
            float p3 = Ps[(ty * 4 + 3) * 68 + kk];
            float4 ga = *(const float4*)&Gs[kk * 128 + tx * 8];
            float4 gb = *(const float4*)&Gs[kk * 128 + tx * 8 + 4];
            o[0][0] = fmaf(p0, ga.x, o[0][0]); o[0][1] = fmaf(p0, ga.y, o[0][1]);
            o[0][2] = fmaf(p0, ga.z, o[0][2]); o[0][3] = fmaf(p0, ga.w, o[0][3]);
            o[0][4] = fmaf(p0, gb.x, o[0][4]); o[0][5] = fmaf(p0, gb.y, o[0][5]);
            o[0][6] = fmaf(p0, gb.z, o[0][6]); o[0][7] = fmaf(p0, gb.w, o[0][7]);
            o[1][0] = fmaf(p1, ga.x, o[1][0]); o[1][1] = fmaf(p1, ga.y, o[1][1]);
            o[1][2] = fmaf(p1, ga.z, o[1][2]); o[1][3] = fmaf(p1, ga.w, o[1][3]);
            o[1][4] = fmaf(p1, gb.x, o[1][4]); o[1][5] = fmaf(p1, gb.y, o[1][5]);
            o[1][6] = fmaf(p1, gb.z, o[1][6]); o[1][7] = fmaf(p1, gb.w, o[1][7]);
            o[2][0] = fmaf(p2, ga.x, o[2][0]); o[2][1] = fmaf(p2, ga.y, o[2][1]);
            o[2][2] = fmaf(p2, ga.z, o[2][2]); o[2][3] = fmaf(p2, ga.w, o[2][3]);
            o[2][4] = fmaf(p2, gb.x, o[2][4]); o[2][5] = fmaf(p2, gb.y, o[2][5]);
            o[2][6] = fmaf(p2, gb.z, o[2][6]); o[2][7] = fmaf(p2, gb.w, o[2][7]);
            o[3][0] = fmaf(p3, ga.x, o[3][0]); o[3][1] = fmaf(p3, ga.y, o[3][1]);
            o[3][2] = fmaf(p3, ga.z, o[3][2]); o[3][3] = fmaf(p3, ga.w, o[3][3]);
            o[3][4] = fmaf(p3, gb.x, o[3][4]); o[3][5] = fmaf(p3, gb.y, o[3][5]);
            o[3][6] = fmaf(p3, gb.z, o[3][6]); o[3][7] = fmaf(p3, gb.w, o[3][7]);
        }
        __syncthreads();
    }

#pragma unroll
    for (int i = 0; i < 4; i++) {
        float inv = 1.f / l_reg[i];
        size_t row = (size_t)b * 4096 + qt * 64 + ty * 4 + i;
        float4 v0 = make_float4(o[i][0] * inv, o[i][1] * inv, o[i][2] * inv, o[i][3] * inv);
        float4 v1 = make_float4(o[i][4] * inv, o[i][5] * inv, o[i][6] * inv, o[i][7] * inv);
        *(float4*)(Y + row * 128 + tx * 8) = v0;
        *(float4*)(Y + row * 128 + tx * 8 + 4) = v1;
    }
}

// ---------------- kernel 5: out = elu(bn2(Y)) @ W_z + b_z, *sita + inputs ----------------
__global__ void __launch_bounds__(256) k_gemm_z(
    const float* __restrict__ A, const float* __restrict__ W, const float* __restrict__ bias,
    const float* __restrict__ g2, const float* __restrict__ b2,
    const float* __restrict__ m2, const float* __restrict__ v2,
    const float* __restrict__ sita, const float* __restrict__ resid, float* __restrict__ out)
{
    const int K = 128, N = 256;
    int m0 = blockIdx.x * 128;
    int n0 = blockIdx.y * 128;
    __shared__ float As[8][128];
    __shared__ float Bs[8][128];
    int tid = threadIdx.x;
    int ty = tid >> 4, tx = tid & 15;
    float st = *sita;

    float acc[8][8];
#pragma unroll
    for (int i = 0; i < 8; i++)
#pragma unroll
        for (int j = 0; j < 8; j++) acc[i][j] = 0.f;

    for (int k0 = 0; k0 < K; k0 += 8) {
        {
            int r = tid >> 1, kc = (tid & 1) * 4;
            int c = k0 + kc;
            float4 v = *(const float4*)(A + (size_t)(m0 + r) * K + c);
            v.x = elu_f(fmaf(v.x - m2[c + 0], g2[c + 0] * rsqrtf(v2[c + 0] + EPS), b2[c + 0]));
            v.y = elu_f(fmaf(v.y - m2[c + 1], g2[c + 1] * rsqrtf(v2[c + 1] + EPS), b2[c + 1]));
            v.z = elu_f(fmaf(v.z - m2[c + 2], g2[c + 2] * rsqrtf(v2[c + 2] + EPS), b2[c + 2]));
            v.w = elu_f(fmaf(v.w - m2[c + 3], g2[c + 3] * rsqrtf(v2[c + 3] + EPS), b2[c + 3]));
            As[kc + 0][r] = v.x; As[kc + 1][r] = v.y; As[kc + 2][r] = v.z; As[kc + 3][r] = v.w;
            int kr = tid >> 5, col = (tid & 31) * 4;
            float4 w = *(const float4*)(W + (size_t)(k0 + kr) * N + n0 + col);
            *(float4*)&Bs[kr][col] = w;
        }
        __syncthreads();
#pragma unroll
        for (int kk = 0; kk < 8; ++kk) {
            float a[8], b[8];
            *(float4*)&a[0] = *(const float4*)&As[kk][ty * 8];
            *(float4*)&a[4] = *(const float4*)&As[kk][ty * 8 + 4];
            *(float4*)&b[0] = *(const float4*)&Bs[kk][tx * 8];
            *(float4*)&b[4] = *(const float4*)&Bs[kk][tx * 8 + 4];
#pragma unroll
            for (int i = 0; i < 8; i++)
#pragma unroll
                for (int j = 0; j < 8; j++)
                    acc[i][j] = fmaf(a[i], b[j], acc[i][j]);
        }
        __syncthreads();
    }

#pragma unroll
    for (int i = 0; i < 8; i++) {
        size_t row = (size_t)(m0 + ty * 8 + i);
#pragma unroll
        for (int j = 0; j < 8; j += 4) {
            int col = n0 + tx * 8 + j;
            float4 r = *(const float4*)(resid + row * 256 + col);
            float4 v = make_float4(fmaf(acc[i][j + 0] + bias[col + 0], st, r.x),
                                   fmaf(acc[i][j + 1] + bias[col + 1], st, r.y),
                                   fmaf(acc[i][j + 2] + bias[col + 2], st, r.z),
                                   fmaf(acc[i][j + 3] + bias[col + 3], st, r.w));
            *(float4*)(out + row * 256 + col) = v;
        }
    }
}

// ---------------- launcher ----------------
extern "C" void kernel_launch(void* const* d_in, const int* in_sizes, int n_in,
                              void* d_out, int out_size)
{
    const float* inputs = (const float*)d_in[0];
    const float* bn1g = (const float*)d_in[1];
    const float* bn1b = (const float*)d_in[2];
    const float* bn1m = (const float*)d_in[3];
    const float* bn1v = (const float*)d_in[4];
    const float* bn2g = (const float*)d_in[5];
    const float* bn2b = (const float*)d_in[6];
    const float* bn2m = (const float*)d_in[7];
    const float* bn2v = (const float*)d_in[8];
    const float* Wg   = (const float*)d_in[9];
    const float* bg   = (const float*)d_in[10];
    const float* Wth  = (const float*)d_in[11];
    const float* bth  = (const float*)d_in[12];
    const float* Wph  = (const float*)d_in[13];
    const float* bph  = (const float*)d_in[14];
    const float* Wz   = (const float*)d_in[15];
    const float* bz   = (const float*)d_in[16];
    const float* sita = (const float*)d_in[17];
    float* out = (float*)d_out;

    float *X, *theta, *gfull, *phifull, *gpool, *phipool, *Y;
    cudaGetSymbolAddress((void**)&X, g_X);
    cudaGetSymbolAddress((void**)&theta, g_theta);
    cudaGetSymbolAddress((void**)&gfull, g_gfull);
    cudaGetSymbolAddress((void**)&phifull, g_phifull);
    cudaGetSymbolAddress((void**)&gpool, g_gpool);
    cudaGetSymbolAddress((void**)&phipool, g_phipool);
    cudaGetSymbolAddress((void**)&Y, g_Y);

    cudaFuncSetAttribute(k_attn, cudaFuncAttributeMaxDynamicSharedMemorySize, ATTN_SMEM_BYTES);

    // 1) bn1 + elu
    k_bn1_elu<<<8192, 256>>>((const float4*)inputs, bn1g, bn1b, bn1m, bn1v, (float4*)X);
    // 2) theta / g / phi convs
    k_gemm3<<<dim3(256, 3), 256>>>(X, Wth, bth, theta, Wg, bg, gfull, Wph, bph, phifull);
    // 3) maxpool width 2
    k_pool<<<2048, 256>>>((const float4*)gfull, (const float4*)phifull,
                          (float4*)gpool, (float4*)phipool);
    // 4) attention
    k_attn<<<dim3(64, 8), 256, ATTN_SMEM_BYTES>>>(theta, phipool, gpool, Y);
    // 5) bn2+elu -> W_z -> *sita + residual
    k_gemm_z<<<dim3(256, 2), 256>>>(Y, Wz, bz, bn2g, bn2b, bn2m, bn2v, sita, inputs, out);
}

// round 3
// speedup vs baseline: 3.5254x; 3.5254x over previous
#include <cuda_runtime.h>
#include <cuda_fp16.h>
#include <math.h>

#define EPS 1e-3f

// ---------------- scratch (device globals) ----------------
__device__ float  g_X[8 * 4096 * 256];          // bn1+elu(inputs), fp32
__device__ __half g_theta[8 * 4096 * 128];      // Q, fp16
__device__ __half g_gfull[8 * 4096 * 128];      // g conv out (pre-pool), fp16
__device__ __half g_phifull[8 * 4096 * 128];    // phi conv out (pre-pool), fp16
__device__ __half g_phipool[8 * 2048 * 128];    // K [b][key][ch], fp16
__device__ __half g_gT[8 * 128 * 2048];         // V transposed [b][ch][key], fp16
__device__ float  g_Y[8 * 4096 * 128];          // attention out, fp32

__device__ __forceinline__ float elu_f(float v) { return v > 0.f ? v : expm1f(v); }

// ---------------- kernel 1: x = elu(bn1(inputs)) ----------------
__global__ void __launch_bounds__(256) k_bn1_elu(
    const float4* __restrict__ in,
    const float* __restrict__ gamma, const float* __restrict__ beta,
    const float* __restrict__ mean, const float* __restrict__ var,
    float4* __restrict__ X)
{
    int i = blockIdx.x * 256 + threadIdx.x;
    int c = (i & 63) * 4;
    float4 v = in[i];
    float4 o;
    o.x = elu_f(fmaf(v.x - mean[c + 0], gamma[c + 0] * rsqrtf(var[c + 0] + EPS), beta[c + 0]));
    o.y = elu_f(fmaf(v.y - mean[c + 1], gamma[c + 1] * rsqrtf(var[c + 1] + EPS), beta[c + 1]));
    o.z = elu_f(fmaf(v.z - mean[c + 2], gamma[c + 2] * rsqrtf(var[c + 2] + EPS), beta[c + 2]));
    o.w = elu_f(fmaf(v.w - mean[c + 3], gamma[c + 3] * rsqrtf(var[c + 3] + EPS), beta[c + 3]));
    X[i] = o;
}

// ---------------- kernel 2: three 1x1 convs, SGEMM [32768,256]x[256,128], fp16 out ----------------
__global__ void __launch_bounds__(256) k_gemm3(
    const float* __restrict__ A,
    const float* __restrict__ W0, const float* __restrict__ b0, __half* __restrict__ C0,
    const float* __restrict__ W1, const float* __restrict__ b1, __half* __restrict__ C1,
    const float* __restrict__ W2, const float* __restrict__ b2, __half* __restrict__ C2)
{
    const float* W; const float* bias; __half* C;
    if (blockIdx.y == 0)      { W = W0; bias = b0; C = C0; }
    else if (blockIdx.y == 1) { W = W1; bias = b1; C = C1; }
    else                      { W = W2; bias = b2; C = C2; }

    const int K = 256, N = 128;
    int m0 = blockIdx.x * 128;
    __shared__ float As[8][128];
    __shared__ float Bs[8][128];
    int tid = threadIdx.x;
    int ty = tid >> 4, tx = tid & 15;

    float acc[8][8];
#pragma unroll
    for (int i = 0; i < 8; i++)
#pragma unroll
        for (int j = 0; j < 8; j++) acc[i][j] = 0.f;

    for (int k0 = 0; k0 < K; k0 += 8) {
        {
            int r = tid >> 1, kc = (tid & 1) * 4;
            float4 v = *(const float4*)(A + (size_t)(m0 + r) * K + k0 + kc);
            As[kc + 0][r] = v.x; As[kc + 1][r] = v.y; As[kc + 2][r] = v.z; As[kc + 3][r] = v.w;
            int kr = tid >> 5, col = (tid & 31) * 4;
            float4 w = *(const float4*)(W + (size_t)(k0 + kr) * N + col);
            *(float4*)&Bs[kr][col] = w;
        }
        __syncthreads();
#pragma unroll
        for (int kk = 0; kk < 8; ++kk) {
            float a[8], b[8];
            *(float4*)&a[0] = *(const float4*)&As[kk][ty * 8];
            *(float4*)&a[4] = *(const float4*)&As[kk][ty * 8 + 4];
            *(float4*)&b[0] = *(const float4*)&Bs[kk][tx * 8];
            *(float4*)&b[4] = *(const float4*)&Bs[kk][tx * 8 + 4];
#pragma unroll
            for (int i = 0; i < 8; i++)
#pragma unroll
                for (int j = 0; j < 8; j++)
                    acc[i][j] = fmaf(a[i], b[j], acc[i][j]);
        }
        __syncthreads();
    }

#pragma unroll
    for (int i = 0; i < 8; i++) {
        size_t row = (size_t)(m0 + ty * 8 + i);
        int col = tx * 8;
        __half2 h0 = __floats2half2_rn(acc[i][0] + bias[col + 0], acc[i][1] + bias[col + 1]);
        __half2 h1 = __floats2half2_rn(acc[i][2] + bias[col + 2], acc[i][3] + bias[col + 3]);
        __half2 h2 = __floats2half2_rn(acc[i][4] + bias[col + 4], acc[i][5] + bias[col + 5]);
        __half2 h3 = __floats2half2_rn(acc[i][6] + bias[col + 6], acc[i][7] + bias[col + 7]);
        uint4 u;
        u.x = *(unsigned*)&h0; u.y = *(unsigned*)&h1;
        u.z = *(unsigned*)&h2; u.w = *(unsigned*)&h3;
        *(uint4*)(C + row * 128 + col) = u;
    }
}

// ---------------- kernel 3: pool (w2) for phi -> [key][ch]; pool+transpose for g -> [ch][key] ----------------
// block = 64 keys x 128 ch; grid (32 key-tiles, 8 batches)
#define GP 136  // padded halves per smem row
__global__ void __launch_bounds__(256) k_pool(
    const __half* __restrict__ gfull, const __half* __restrict__ phifull,
    __half* __restrict__ phipool, __half* __restrict__ gT)
{
    __shared__ __half Gs[64 * GP];
    int b = blockIdx.y, k0 = blockIdx.x * 64;
    int tid = threadIdx.x;

    union H8 { float4 f; __half2 h[4]; };

    for (int i = tid; i < 64 * 16; i += 256) {
        int r = i >> 4, c8 = (i & 15) * 8;
        int key = k0 + r;
        int h = key >> 5, w2 = key & 31;
        size_t p0 = ((size_t)b * 4096 + (h * 64 + 2 * w2)) * 128 + c8;
        H8 a, c, res;
        a.f = *(const float4*)(gfull + p0);
        c.f = *(const float4*)(gfull + p0 + 128);
#pragma unroll
        for (int k = 0; k < 4; k++) res.h[k] = __hmax2(a.h[k], c.h[k]);
        *(float4*)(Gs + r * GP + c8) = res.f;
        a.f = *(const float4*)(phifull + p0);
        c.f = *(const float4*)(phifull + p0 + 128);
#pragma unroll
        for (int k = 0; k < 4; k++) res.h[k] = __hmax2(a.h[k], c.h[k]);
        *(float4*)(phipool + ((size_t)b * 2048 + key) * 128 + c8) = res.f;
    }
    __syncthreads();

    // transpose: thread tid<128 owns channel=tid, writes 64 keys contiguous
    if (tid < 128) {
        int ch = tid;
        __half tmp[64];
#pragma unroll
        for (int k = 0; k < 64; k++) tmp[k] = Gs[k * GP + ch];
        float4* dst = (float4*)(gT + ((size_t)(b * 128 + ch)) * 2048 + k0);
        const float4* src = (const float4*)tmp;
#pragma unroll
        for (int i = 0; i < 8; i++) dst[i] = src[i];
    }
}

// ---------------- kernel 4: flash attention with mma.sync fp16 ----------------
// block: 128 queries, 8 warps (16 rows each); key tiles of 64; ch = 128.
#define QPAD 136
#define KPAD 136
#define GPAD 72
#define ATTN_SMEM ((128 * QPAD + 64 * KPAD + 128 * GPAD) * 2)

__device__ __forceinline__ void mma16816(float* c, const unsigned* a, unsigned b0, unsigned b1) {
    asm volatile(
        "mma.sync.aligned.m16n8k16.row.col.f32.f16.f16.f32 "
        "{%0,%1,%2,%3}, {%4,%5,%6,%7}, {%8,%9}, {%0,%1,%2,%3};"
        : "+f"(c[0]), "+f"(c[1]), "+f"(c[2]), "+f"(c[3])
        : "r"(a[0]), "r"(a[1]), "r"(a[2]), "r"(a[3]), "r"(b0), "r"(b1));
}

__global__ void __launch_bounds__(256, 1) k_attn(
    const __half* __restrict__ theta, const __half* __restrict__ phiK,
    const __half* __restrict__ gT, float* __restrict__ Y)
{
    extern __shared__ __half sm[];
    __half* Qs = sm;                       // [128][QPAD]
    __half* Ks = sm + 128 * QPAD;          // [64][KPAD]
    __half* Gs = sm + 128 * QPAD + 64 * KPAD;  // [128][GPAD] (channel rows, 64 keys)

    int b = blockIdx.y, qt = blockIdx.x;
    int tid = threadIdx.x;
    int w = tid >> 5, l = tid & 31;
    int g = l >> 2, t = l & 3;

    // load Q tile [128][128] fp16
    const __half* Qg = theta + ((size_t)b * 4096 + qt * 128) * 128;
    for (int i = tid; i < 128 * 16; i += 256) {
        int r = i >> 4, c8 = (i & 15) * 8;
        *(float4*)(Qs + r * QPAD + c8) = *(const float4*)(Qg + r * 128 + c8);
    }
    __syncthreads();

    // preload Q A-fragments (persist across all key tiles)
    unsigned a_q[8][4];
    int qrow = w * 16 + g;
#pragma unroll
    for (int s = 0; s < 8; s++) {
        a_q[s][0] = *(const unsigned*)(Qs + qrow * QPAD + s * 16 + 2 * t);
        a_q[s][1] = *(const unsigned*)(Qs + (qrow + 8) * QPAD + s * 16 + 2 * t);
        a_q[s][2] = *(const unsigned*)(Qs + qrow * QPAD + s * 16 + 8 + 2 * t);
        a_q[s][3] = *(const unsigned*)(Qs + (qrow + 8) * QPAD + s * 16 + 8 + 2 * t);
    }

    float o[16][4];
#pragma unroll
    for (int j = 0; j < 16; j++)
#pragma unroll
        for (int q = 0; q < 4; q++) o[j][q] = 0.f;
    float m0r = -1e30f, m1r = -1e30f, l0 = 0.f, l1 = 0.f;

    const __half* Kg = phiK + (size_t)b * 2048 * 128;
    const __half* Gg = gT + (size_t)b * 128 * 2048;

    for (int kt = 0; kt < 32; ++kt) {
        __syncthreads();  // everyone done reading previous K/G tiles
        const __half* Kt = Kg + (size_t)kt * 64 * 128;
        for (int i = tid; i < 64 * 16; i += 256) {
            int r = i >> 4, c8 = (i & 15) * 8;
            *(float4*)(Ks + r * KPAD + c8) = *(const float4*)(Kt + r * 128 + c8);
        }
        for (int i = tid; i < 128 * 8; i += 256) {
            int r = i >> 3, c8 = (i & 7) * 8;
            *(float4*)(Gs + r * GPAD + c8) = *(const float4*)(Gg + (size_t)r * 2048 + kt * 64 + c8);
        }
        __syncthreads();

        // --- S = Q @ K^T : 8 n-tiles (64 keys), 8 k-steps (128 ch) ---
        float c[8][4];
#pragma unroll
        for (int j = 0; j < 8; j++)
#pragma unroll
            for (int q = 0; q < 4; q++) c[j][q] = 0.f;
#pragma unroll
        for (int s = 0; s < 8; s++) {
#pragma unroll
            for (int j = 0; j < 8; j++) {
                unsigned b0 = *(const unsigned*)(Ks + (8 * j + g) * KPAD + s * 16 + 2 * t);
                unsigned b1 = *(const unsigned*)(Ks + (8 * j + g) * KPAD + s * 16 + 8 + 2 * t);
                mma16816(c[j], a_q[s], b0, b1);
            }
        }

        // --- online softmax (rows g and g+8 of this warp's 16) ---
        float rmax0 = -1e30f, rmax1 = -1e30f;
#pragma unroll
        for (int j = 0; j < 8; j++) {
            rmax0 = fmaxf(rmax0, fmaxf(c[j][0], c[j][1]));
            rmax1 = fmaxf(rmax1, fmaxf(c[j][2], c[j][3]));
        }
        rmax0 = fmaxf(rmax0, __shfl_xor_sync(0xffffffffu, rmax0, 1));
        rmax0 = fmaxf(rmax0, __shfl_xor_sync(0xffffffffu, rmax0, 2));
        rmax1 = fmaxf(rmax1, __shfl_xor_sync(0xffffffffu, rmax1, 1));
        rmax1 = fmaxf(rmax1, __shfl_xor_sync(0xffffffffu, rmax1, 2));
        float mn0 = fmaxf(m0r, rmax0), mn1 = fmaxf(m1r, rmax1);
        float al0 = __expf(m0r - mn0), al1 = __expf(m1r - mn1);
        m0r = mn0; m1r = mn1;

        float s0 = 0.f, s1 = 0.f;
        unsigned P0[8], P1[8];
#pragma unroll
        for (int j = 0; j < 8; j++) {
            float p0 = __expf(c[j][0] - mn0);
            float p1 = __expf(c[j][1] - mn0);
            float p2 = __expf(c[j][2] - mn1);
            float p3 = __expf(c[j][3] - mn1);
            s0 += p0 + p1; s1 += p2 + p3;
            __half2 h01 = __floats2half2_rn(p0, p1);
            __half2 h23 = __floats2half2_rn(p2, p3);
            P0[j] = *(unsigned*)&h01;
            P1[j] = *(unsigned*)&h23;
        }
        s0 += __shfl_xor_sync(0xffffffffu, s0, 1);
        s0 += __shfl_xor_sync(0xffffffffu, s0, 2);
        s1 += __shfl_xor_sync(0xffffffffu, s1, 1);
        s1 += __shfl_xor_sync(0xffffffffu, s1, 2);
        l0 = l0 * al0 + s0;
        l1 = l1 * al1 + s1;
#pragma unroll
        for (int j = 0; j < 16; j++) {
            o[j][0] *= al0; o[j][1] *= al0;
            o[j][2] *= al1; o[j][3] *= al1;
        }

        // --- O += P @ G : A = P (regs), B from Gs[ch][key]; 16 n-tiles (128 ch), 4 k-steps (64 keys) ---
#pragma unroll
        for (int s = 0; s < 4; s++) {
            unsigned pa[4] = { P0[2 * s], P1[2 * s], P0[2 * s + 1], P1[2 * s + 1] };
#pragma unroll
            for (int j = 0; j < 16; j++) {
                unsigned b0 = *(const unsigned*)(Gs + (8 * j + g) * GPAD + s * 16 + 2 * t);
                unsigned b1 = *(const unsigned*)(Gs + (8 * j + g) * GPAD + s * 16 + 8 + 2 * t);
                mma16816(o[j], pa, b0, b1);
            }
        }
    }

    // epilogue: normalize and store fp32
    float inv0 = 1.f / l0, inv1 = 1.f / l1;
    size_t base = (size_t)b * 4096 + qt * 128 + w * 16;
#pragma unroll
    for (int j = 0; j < 16; j++) {
        float2 v0 = make_float2(o[j][0] * inv0, o[j][1] * inv0);
        float2 v1 = make_float2(o[j][2] * inv1, o[j][3] * inv1);
        *(float2*)(Y + (base + g) * 128 + j * 8 + 2 * t) = v0;
        *(float2*)(Y + (base + g + 8) * 128 + j * 8 + 2 * t) = v1;
    }
}

// ---------------- kernel 5: out = elu(bn2(Y)) @ W_z + b_z, *sita + inputs ----------------
__global__ void __launch_bounds__(256) k_gemm_z(
    const float* __restrict__ A, const float* __restrict__ W, const float* __restrict__ bias,
    const float* __restrict__ g2, const float* __restrict__ b2,
    const float* __restrict__ m2, const float* __restrict__ v2,
    const float* __restrict__ sita, const float* __restrict__ resid, float* __restrict__ out)
{
    const int K = 128, N = 256;
    int m0 = blockIdx.x * 128;
    int n0 = blockIdx.y * 128;
    __shared__ float As[8][128];
    __shared__ float Bs[8][128];
    int tid = threadIdx.x;
    int ty = tid >> 4, tx = tid & 15;
    float st = *sita;

    float acc[8][8];
#pragma unroll
    for (int i = 0; i < 8; i++)
#pragma unroll
        for (int j = 0; j < 8; j++) acc[i][j] = 0.f;

    for (int k0 = 0; k0 < K; k0 += 8) {
        {
            int r = tid >> 1, kc = (tid & 1) * 4;
            int c = k0 + kc;
            float4 v = *(const float4*)(A + (size_t)(m0 + r) * K + c);
            v.x = elu_f(fmaf(v.x - m2[c + 0], g2[c + 0] * rsqrtf(v2[c + 0] + EPS), b2[c + 0]));
            v.y = elu_f(fmaf(v.y - m2[c + 1], g2[c + 1] * rsqrtf(v2[c + 1] + EPS), b2[c + 1]));
            v.z = elu_f(fmaf(v.z - m2[c + 2], g2[c + 2] * rsqrtf(v2[c + 2] + EPS), b2[c + 2]));
            v.w = elu_f(fmaf(v.w - m2[c + 3], g2[c + 3] * rsqrtf(v2[c + 3] + EPS), b2[c + 3]));
            As[kc + 0][r] = v.x; As[kc + 1][r] = v.y; As[kc + 2][r] = v.z; As[kc + 3][r] = v.w;
            int kr = tid >> 5, col = (tid & 31) * 4;
            float4 w = *(const float4*)(W + (size_t)(k0 + kr) * N + n0 + col);
            *(float4*)&Bs[kr][col] = w;
        }
        __syncthreads();
#pragma unroll
        for (int kk = 0; kk < 8; ++kk) {
            float a[8], b[8];
            *(float4*)&a[0] = *(const float4*)&As[kk][ty * 8];
            *(float4*)&a[4] = *(const float4*)&As[kk][ty * 8 + 4];
            *(float4*)&b[0] = *(const float4*)&Bs[kk][tx * 8];
            *(float4*)&b[4] = *(const float4*)&Bs[kk][tx * 8 + 4];
#pragma unroll
            for (int i = 0; i < 8; i++)
#pragma unroll
                for (int j = 0; j < 8; j++)
                    acc[i][j] = fmaf(a[i], b[j], acc[i][j]);
        }
        __syncthreads();
    }

#pragma unroll
    for (int i = 0; i < 8; i++) {
        size_t row = (size_t)(m0 + ty * 8 + i);
#pragma unroll
        for (int j = 0; j < 8; j += 4) {
            int col = n0 + tx * 8 + j;
            float4 r = *(const float4*)(resid + row * 256 + col);
            float4 v = make_float4(fmaf(acc[i][j + 0] + bias[col + 0], st, r.x),
                                   fmaf(acc[i][j + 1] + bias[col + 1], st, r.y),
                                   fmaf(acc[i][j + 2] + bias[col + 2], st, r.z),
                                   fmaf(acc[i][j + 3] + bias[col + 3], st, r.w));
            *(float4*)(out + row * 256 + col) = v;
        }
    }
}

// ---------------- launcher ----------------
extern "C" void kernel_launch(void* const* d_in, const int* in_sizes, int n_in,
                              void* d_out, int out_size)
{
    const float* inputs = (const float*)d_in[0];
    const float* bn1g = (const float*)d_in[1];
    const float* bn1b = (const float*)d_in[2];
    const float* bn1m = (const float*)d_in[3];
    const float* bn1v = (const float*)d_in[4];
    const float* bn2g = (const float*)d_in[5];
    const float* bn2b = (const float*)d_in[6];
    const float* bn2m = (const float*)d_in[7];
    const float* bn2v = (const float*)d_in[8];
    const float* Wg   = (const float*)d_in[9];
    const float* bg   = (const float*)d_in[10];
    const float* Wth  = (const float*)d_in[11];
    const float* bth  = (const float*)d_in[12];
    const float* Wph  = (const float*)d_in[13];
    const float* bph  = (const float*)d_in[14];
    const float* Wz   = (const float*)d_in[15];
    const float* bz   = (const float*)d_in[16];
    const float* sita = (const float*)d_in[17];
    float* out = (float*)d_out;

    float *X, *Y;
    __half *theta, *gfull, *phifull, *phipool, *gT;
    cudaGetSymbolAddress((void**)&X, g_X);
    cudaGetSymbolAddress((void**)&theta, g_theta);
    cudaGetSymbolAddress((void**)&gfull, g_gfull);
    cudaGetSymbolAddress((void**)&phifull, g_phifull);
    cudaGetSymbolAddress((void**)&phipool, g_phipool);
    cudaGetSymbolAddress((void**)&gT, g_gT);
    cudaGetSymbolAddress((void**)&Y, g_Y);

    cudaFuncSetAttribute(k_attn, cudaFuncAttributeMaxDynamicSharedMemorySize, ATTN_SMEM);

    // 1) bn1 + elu
    k_bn1_elu<<<8192, 256>>>((const float4*)inputs, bn1g, bn1b, bn1m, bn1v, (float4*)X);
    // 2) theta / g / phi convs (fp16 outputs)
    k_gemm3<<<dim3(256, 3), 256>>>(X, Wth, bth, theta, Wg, bg, gfull, Wph, bph, phifull);
    // 3) pool (+transpose for g)
    k_pool<<<dim3(32, 8), 256>>>(gfull, phifull, phipool, gT);
    // 4) flash attention (tensor cores)
    k_attn<<<dim3(32, 8), 256, ATTN_SMEM>>>(theta, phipool, gT, Y);
    // 5) bn2+elu -> W_z -> *sita + residual
    k_gemm_z<<<dim3(256, 2), 256>>>(Y, Wz, bz, bn2g, bn2b, bn2m, bn2v, sita, inputs, out);
}

// round 4
// speedup vs baseline: 4.5709x; 1.2966x over previous
#include <cuda_runtime.h>
#include <cuda_fp16.h>
#include <math.h>

#define EPS 1e-3f

// ---------------- scratch (device globals) ----------------
__device__ float  g_X[8 * 4096 * 256];          // bn1+elu(inputs), fp32
__device__ __half g_theta[8 * 4096 * 128];      // Q, fp16
__device__ __half g_gfull[8 * 4096 * 128];      // g conv out (pre-pool), fp16
__device__ __half g_phifull[8 * 4096 * 128];    // phi conv out (pre-pool), fp16
__device__ __half g_phipool[8 * 2048 * 128];    // K [b][key][ch], fp16
__device__ __half g_gT[8 * 128 * 2048];         // V transposed [b][ch][key], fp16
__device__ float  g_Y[8 * 4096 * 128];          // attention out, fp32

__device__ __forceinline__ float elu_f(float v) { return v > 0.f ? v : expm1f(v); }

// ---------------- kernel 1: x = elu(bn1(inputs)) ----------------
__global__ void __launch_bounds__(256) k_bn1_elu(
    const float4* __restrict__ in,
    const float* __restrict__ gamma, const float* __restrict__ beta,
    const float* __restrict__ mean, const float* __restrict__ var,
    float4* __restrict__ X)
{
    int i = blockIdx.x * 256 + threadIdx.x;
    int c = (i & 63) * 4;
    float4 v = in[i];
    float4 o;
    o.x = elu_f(fmaf(v.x - mean[c + 0], gamma[c + 0] * rsqrtf(var[c + 0] + EPS), beta[c + 0]));
    o.y = elu_f(fmaf(v.y - mean[c + 1], gamma[c + 1] * rsqrtf(var[c + 1] + EPS), beta[c + 1]));
    o.z = elu_f(fmaf(v.z - mean[c + 2], gamma[c + 2] * rsqrtf(var[c + 2] + EPS), beta[c + 2]));
    o.w = elu_f(fmaf(v.w - mean[c + 3], gamma[c + 3] * rsqrtf(var[c + 3] + EPS), beta[c + 3]));
    X[i] = o;
}

// ---------------- kernel 2: three 1x1 convs, SGEMM [32768,256]x[256,128], fp16 out ----------------
__global__ void __launch_bounds__(256) k_gemm3(
    const float* __restrict__ A,
    const float* __restrict__ W0, const float* __restrict__ b0, __half* __restrict__ C0,
    const float* __restrict__ W1, const float* __restrict__ b1, __half* __restrict__ C1,
    const float* __restrict__ W2, const float* __restrict__ b2, __half* __restrict__ C2)
{
    const float* W; const float* bias; __half* C;
    if (blockIdx.y == 0)      { W = W0; bias = b0; C = C0; }
    else if (blockIdx.y == 1) { W = W1; bias = b1; C = C1; }
    else                      { W = W2; bias = b2; C = C2; }

    const int K = 256, N = 128;
    int m0 = blockIdx.x * 128;
    __shared__ float As[8][128];
    __shared__ float Bs[8][128];
    int tid = threadIdx.x;
    int ty = tid >> 4, tx = tid & 15;

    float acc[8][8];
#pragma unroll
    for (int i = 0; i < 8; i++)
#pragma unroll
        for (int j = 0; j < 8; j++) acc[i][j] = 0.f;

    for (int k0 = 0; k0 < K; k0 += 8) {
        {
            int r = tid >> 1, kc = (tid & 1) * 4;
            float4 v = *(const float4*)(A + (size_t)(m0 + r) * K + k0 + kc);
            As[kc + 0][r] = v.x; As[kc + 1][r] = v.y; As[kc + 2][r] = v.z; As[kc + 3][r] = v.w;
            int kr = tid >> 5, col = (tid & 31) * 4;
            float4 w = *(const float4*)(W + (size_t)(k0 + kr) * N + col);
            *(float4*)&Bs[kr][col] = w;
        }
        __syncthreads();
#pragma unroll
        for (int kk = 0; kk < 8; ++kk) {
            float a[8], b[8];
            *(float4*)&a[0] = *(const float4*)&As[kk][ty * 8];
            *(float4*)&a[4] = *(const float4*)&As[kk][ty * 8 + 4];
            *(float4*)&b[0] = *(const float4*)&Bs[kk][tx * 8];
            *(float4*)&b[4] = *(const float4*)&Bs[kk][tx * 8 + 4];
#pragma unroll
            for (int i = 0; i < 8; i++)
#pragma unroll
                for (int j = 0; j < 8; j++)
                    acc[i][j] = fmaf(a[i], b[j], acc[i][j]);
        }
        __syncthreads();
    }

#pragma unroll
    for (int i = 0; i < 8; i++) {
        size_t row = (size_t)(m0 + ty * 8 + i);
        int col = tx * 8;
        __half2 h0 = __floats2half2_rn(acc[i][0] + bias[col + 0], acc[i][1] + bias[col + 1]);
        __half2 h1 = __floats2half2_rn(acc[i][2] + bias[col + 2], acc[i][3] + bias[col + 3]);
        __half2 h2 = __floats2half2_rn(acc[i][4] + bias[col + 4], acc[i][5] + bias[col + 5]);
        __half2 h3 = __floats2half2_rn(acc[i][6] + bias[col + 6], acc[i][7] + bias[col + 7]);
        uint4 u;
        u.x = *(unsigned*)&h0; u.y = *(unsigned*)&h1;
        u.z = *(unsigned*)&h2; u.w = *(unsigned*)&h3;
        *(uint4*)(C + row * 128 + col) = u;
    }
}

// ---------------- kernel 3: pool (w2) for phi -> [key][ch]; pool+transpose for g -> [ch][key] ----------------
#define GP 136
__global__ void __launch_bounds__(256) k_pool(
    const __half* __restrict__ gfull, const __half* __restrict__ phifull,
    __half* __restrict__ phipool, __half* __restrict__ gT)
{
    __shared__ __half Gs[64 * GP];
    int b = blockIdx.y, k0 = blockIdx.x * 64;
    int tid = threadIdx.x;

    union H8 { float4 f; __half2 h[4]; };

    for (int i = tid; i < 64 * 16; i += 256) {
        int r = i >> 4, c8 = (i & 15) * 8;
        int key = k0 + r;
        int h = key >> 5, w2 = key & 31;
        size_t p0 = ((size_t)b * 4096 + (h * 64 + 2 * w2)) * 128 + c8;
        H8 a, c, res;
        a.f = *(const float4*)(gfull + p0);
        c.f = *(const float4*)(gfull + p0 + 128);
#pragma unroll
        for (int k = 0; k < 4; k++) res.h[k] = __hmax2(a.h[k], c.h[k]);
        *(float4*)(Gs + r * GP + c8) = res.f;
        a.f = *(const float4*)(phifull + p0);
        c.f = *(const float4*)(phifull + p0 + 128);
#pragma unroll
        for (int k = 0; k < 4; k++) res.h[k] = __hmax2(a.h[k], c.h[k]);
        *(float4*)(phipool + ((size_t)b * 2048 + key) * 128 + c8) = res.f;
    }
    __syncthreads();

    if (tid < 128) {
        int ch = tid;
        __half tmp[64];
#pragma unroll
        for (int k = 0; k < 64; k++) tmp[k] = Gs[k * GP + ch];
        float4* dst = (float4*)(gT + ((size_t)(b * 128 + ch)) * 2048 + k0);
        const float4* src = (const float4*)tmp;
#pragma unroll
        for (int i = 0; i < 8; i++) dst[i] = src[i];
    }
}

// ---------------- kernel 4: flash attention, fp16 mma, cp.async double buffer ----------------
// block: 128 queries, 8 warps (16 rows each); key tiles of 64; ch = 128.
// smem: 2 stages x (K [64][136] + G [128][72]) halves = 71680 B. Q tile reuses stage0.
#define STAGE_H 17920              // halves per stage
#define KOFF 0                     // K at stage base
#define GOFF 8704                  // G after K
#define ATTN_SMEM (2 * STAGE_H * 2)

__device__ __forceinline__ unsigned sptr(const void* p) {
    return (unsigned)__cvta_generic_to_shared(p);
}

__device__ __forceinline__ void mma16816(float* c, const unsigned* a, unsigned b0, unsigned b1) {
    asm volatile(
        "mma.sync.aligned.m16n8k16.row.col.f32.f16.f16.f32 "
        "{%0,%1,%2,%3}, {%4,%5,%6,%7}, {%8,%9}, {%0,%1,%2,%3};"
        : "+f"(c[0]), "+f"(c[1]), "+f"(c[2]), "+f"(c[3])
        : "r"(a[0]), "r"(a[1]), "r"(a[2]), "r"(a[3]), "r"(b0), "r"(b1));
}

__device__ __forceinline__ void mma16816_h(unsigned* c, const unsigned* a, unsigned b0, unsigned b1) {
    asm volatile(
        "mma.sync.aligned.m16n8k16.row.col.f16.f16.f16.f16 "
        "{%0,%1}, {%2,%3,%4,%5}, {%6,%7}, {%0,%1};"
        : "+r"(c[0]), "+r"(c[1])
        : "r"(a[0]), "r"(a[1]), "r"(a[2]), "r"(a[3]), "r"(b0), "r"(b1));
}

__device__ __forceinline__ unsigned ex2h2(float a, float b) {
    __half2 h = __floats2half2_rn(a, b);
    unsigned r;
    asm("ex2.approx.f16x2 %0, %1;" : "=r"(r) : "r"(*(unsigned*)&h));
    return r;
}

__device__ __forceinline__ void issue_stage(__half* sm, int stg, int kt, int tid,
                                            const __half* Kg, const __half* Gg)
{
    __half* Kd = sm + stg * STAGE_H + KOFF;
    __half* Gd = sm + stg * STAGE_H + GOFF;
    const __half* Kt = Kg + (size_t)kt * 64 * 128;
    const __half* Gt = Gg + kt * 64;
#pragma unroll
    for (int u = 0; u < 4; u++) {
        int i = tid + u * 256;             // [0,1024)
        int r = i >> 4, c8 = (i & 15) * 8;
        unsigned d = sptr(Kd + r * 136 + c8);
        asm volatile("cp.async.cg.shared.global [%0], [%1], 16;\n"
                     :: "r"(d), "l"(Kt + r * 128 + c8));
    }
#pragma unroll
    for (int u = 0; u < 4; u++) {
        int i = tid + u * 256;             // [0,1024)
        int ch = i >> 3, c8 = (i & 7) * 8;
        unsigned d = sptr(Gd + ch * 72 + c8);
        asm volatile("cp.async.cg.shared.global [%0], [%1], 16;\n"
                     :: "r"(d), "l"(Gt + (size_t)ch * 2048 + c8));
    }
}

__global__ void __launch_bounds__(256, 2) k_attn(
    const __half* __restrict__ theta, const __half* __restrict__ phiK,
    const __half* __restrict__ gT, float* __restrict__ Y)
{
    extern __shared__ __half sm[];

    int b = blockIdx.y, qt = blockIdx.x;
    int tid = threadIdx.x;
    int w = tid >> 5, l = tid & 31;
    int g = l >> 2, t = l & 3;
    const float L2E = 1.4426950408889634f;

    // --- Q phase: load Q tile into stage area, build register fragments, discard ---
    const __half* Qg = theta + ((size_t)b * 4096 + qt * 128) * 128;
    for (int i = tid; i < 128 * 16; i += 256) {
        int r = i >> 4, c8 = (i & 15) * 8;
        *(float4*)(sm + r * 136 + c8) = *(const float4*)(Qg + r * 128 + c8);
    }
    __syncthreads();

    unsigned a_q[8][4];
    int qrow = w * 16 + g;
#pragma unroll
    for (int s = 0; s < 8; s++) {
        a_q[s][0] = *(const unsigned*)(sm + qrow * 136 + s * 16 + 2 * t);
        a_q[s][1] = *(const unsigned*)(sm + (qrow + 8) * 136 + s * 16 + 2 * t);
        a_q[s][2] = *(const unsigned*)(sm + qrow * 136 + s * 16 + 8 + 2 * t);
        a_q[s][3] = *(const unsigned*)(sm + (qrow + 8) * 136 + s * 16 + 8 + 2 * t);
    }
    __syncthreads();   // all warps done with Q before cp.async overwrites stage0

    const __half* Kg = phiK + (size_t)b * 2048 * 128;
    const __half* Gg = gT + (size_t)b * 128 * 2048;

    // fp16 PV accumulators: oh[j][0] = row g (2 cols), oh[j][1] = row g+8
    unsigned oh[16][2];
#pragma unroll
    for (int j = 0; j < 16; j++) { oh[j][0] = 0u; oh[j][1] = 0u; }
    float m0r = -1e30f, m1r = -1e30f, l0 = 0.f, l1 = 0.f;

    issue_stage(sm, 0, 0, tid, Kg, Gg);
    asm volatile("cp.async.commit_group;\n");

    for (int kt = 0; kt < 32; ++kt) {
        int cur = kt & 1;
        if (kt < 31) {
            issue_stage(sm, cur ^ 1, kt + 1, tid, Kg, Gg);
            asm volatile("cp.async.commit_group;\n");
            asm volatile("cp.async.wait_group 1;\n");
        } else {
            asm volatile("cp.async.wait_group 0;\n");
        }
        __syncthreads();

        const __half* Ks = sm + cur * STAGE_H + KOFF;
        const __half* Gs = sm + cur * STAGE_H + GOFF;

        // --- S = Q @ K^T : fp32 accum ---
        float c[8][4];
#pragma unroll
        for (int j = 0; j < 8; j++)
#pragma unroll
            for (int q = 0; q < 4; q++) c[j][q] = 0.f;
#pragma unroll
        for (int s = 0; s < 8; s++) {
#pragma unroll
            for (int j = 0; j < 8; j++) {
                unsigned b0 = *(const unsigned*)(Ks + (8 * j + g) * 136 + s * 16 + 2 * t);
                unsigned b1 = *(const unsigned*)(Ks + (8 * j + g) * 136 + s * 16 + 8 + 2 * t);
                mma16816(c[j], a_q[s], b0, b1);
            }
        }

        // --- online softmax ---
        float rmax0 = -1e30f, rmax1 = -1e30f;
#pragma unroll
        for (int j = 0; j < 8; j++) {
            rmax0 = fmaxf(rmax0, fmaxf(c[j][0], c[j][1]));
            rmax1 = fmaxf(rmax1, fmaxf(c[j][2], c[j][3]));
        }
        rmax0 = fmaxf(rmax0, __shfl_xor_sync(0xffffffffu, rmax0, 1));
        rmax0 = fmaxf(rmax0, __shfl_xor_sync(0xffffffffu, rmax0, 2));
        rmax1 = fmaxf(rmax1, __shfl_xor_sync(0xffffffffu, rmax1, 1));
        rmax1 = fmaxf(rmax1, __shfl_xor_sync(0xffffffffu, rmax1, 2));
        float mn0 = fmaxf(m0r, rmax0), mn1 = fmaxf(m1r, rmax1);
        float al0 = __expf(m0r - mn0), al1 = __expf(m1r - mn1);
        m0r = mn0; m1r = mn1;
        float mb0 = mn0 * L2E, mb1 = mn1 * L2E;

        unsigned P0[8], P1[8];
        __half2 ps0 = __float2half2_rn(0.f), ps1 = __float2half2_rn(0.f);
#pragma unroll
        for (int j = 0; j < 8; j++) {
            P0[j] = ex2h2(fmaf(c[j][0], L2E, -mb0), fmaf(c[j][1], L2E, -mb0));
            P1[j] = ex2h2(fmaf(c[j][2], L2E, -mb1), fmaf(c[j][3], L2E, -mb1));
            ps0 = __hadd2(ps0, *(__half2*)&P0[j]);
            ps1 = __hadd2(ps1, *(__half2*)&P1[j]);
        }
        float s0 = __low2float(ps0) + __high2float(ps0);
        float s1 = __low2float(ps1) + __high2float(ps1);
        s0 += __shfl_xor_sync(0xffffffffu, s0, 1);
        s0 += __shfl_xor_sync(0xffffffffu, s0, 2);
        s1 += __shfl_xor_sync(0xffffffffu, s1, 1);
        s1 += __shfl_xor_sync(0xffffffffu, s1, 2);
        l0 = l0 * al0 + s0;
        l1 = l1 * al1 + s1;

        __half2 al0h = __float2half2_rn(al0), al1h = __float2half2_rn(al1);
#pragma unroll
        for (int j = 0; j < 16; j++) {
            *(__half2*)&oh[j][0] = __hmul2(*(__half2*)&oh[j][0], al0h);
            *(__half2*)&oh[j][1] = __hmul2(*(__half2*)&oh[j][1], al1h);
        }

        // --- O += P @ G : fp16 accum ---
#pragma unroll
        for (int s = 0; s < 4; s++) {
            unsigned pa[4] = { P0[2 * s], P1[2 * s], P0[2 * s + 1], P1[2 * s + 1] };
#pragma unroll
            for (int j = 0; j < 16; j++) {
                unsigned b0 = *(const unsigned*)(Gs + (8 * j + g) * 72 + s * 16 + 2 * t);
                unsigned b1 = *(const unsigned*)(Gs + (8 * j + g) * 72 + s * 16 + 8 + 2 * t);
                mma16816_h(oh[j], pa, b0, b1);
            }
        }
        __syncthreads();
    }

    // epilogue
    float inv0 = 1.f / l0, inv1 = 1.f / l1;
    size_t base = (size_t)b * 4096 + qt * 128 + w * 16;
#pragma unroll
    for (int j = 0; j < 16; j++) {
        float2 lo = __half22float2(*(__half2*)&oh[j][0]);
        float2 hi = __half22float2(*(__half2*)&oh[j][1]);
        float2 v0 = make_float2(lo.x * inv0, lo.y * inv0);
        float2 v1 = make_float2(hi.x * inv1, hi.y * inv1);
        *(float2*)(Y + (base + g) * 128 + j * 8 + 2 * t) = v0;
        *(float2*)(Y + (base + g + 8) * 128 + j * 8 + 2 * t) = v1;
    }
}

// ---------------- kernel 5: out = elu(bn2(Y)) @ W_z + b_z, *sita + inputs ----------------
__global__ void __launch_bounds__(256) k_gemm_z(
    const float* __restrict__ A, const float* __restrict__ W, const float* __restrict__ bias,
    const float* __restrict__ g2, const float* __restrict__ b2,
    const float* __restrict__ m2, const float* __restrict__ v2,
    const float* __restrict__ sita, const float* __restrict__ resid, float* __restrict__ out)
{
    const int K = 128, N = 256;
    int m0 = blockIdx.x * 128;
    int n0 = blockIdx.y * 128;
    __shared__ float As[8][128];
    __shared__ float Bs[8][128];
    int tid = threadIdx.x;
    int ty = tid >> 4, tx = tid & 15;
    float st = *sita;

    float acc[8][8];
#pragma unroll
    for (int i = 0; i < 8; i++)
#pragma unroll
        for (int j = 0; j < 8; j++) acc[i][j] = 0.f;

    for (int k0 = 0; k0 < K; k0 += 8) {
        {
            int r = tid >> 1, kc = (tid & 1) * 4;
            int c = k0 + kc;
            float4 v = *(const float4*)(A + (size_t)(m0 + r) * K + c);
            v.x = elu_f(fmaf(v.x - m2[c + 0], g2[c + 0] * rsqrtf(v2[c + 0] + EPS), b2[c + 0]));
            v.y = elu_f(fmaf(v.y - m2[c + 1], g2[c + 1] * rsqrtf(v2[c + 1] + EPS), b2[c + 1]));
            v.z = elu_f(fmaf(v.z - m2[c + 2], g2[c + 2] * rsqrtf(v2[c + 2] + EPS), b2[c + 2]));
            v.w = elu_f(fmaf(v.w - m2[c + 3], g2[c + 3] * rsqrtf(v2[c + 3] + EPS), b2[c + 3]));
            As[kc + 0][r] = v.x; As[kc + 1][r] = v.y; As[kc + 2][r] = v.z; As[kc + 3][r] = v.w;
            int kr = tid >> 5, col = (tid & 31) * 4;
            float4 w = *(const float4*)(W + (size_t)(k0 + kr) * N + n0 + col);
            *(float4*)&Bs[kr][col] = w;
        }
        __syncthreads();
#pragma unroll
        for (int kk = 0; kk < 8; ++kk) {
            float a[8], b[8];
            *(float4*)&a[0] = *(const float4*)&As[kk][ty * 8];
            *(float4*)&a[4] = *(const float4*)&As[kk][ty * 8 + 4];
            *(float4*)&b[0] = *(const float4*)&Bs[kk][tx * 8];
            *(float4*)&b[4] = *(const float4*)&Bs[kk][tx * 8 + 4];
#pragma unroll
            for (int i = 0; i < 8; i++)
#pragma unroll
                for (int j = 0; j < 8; j++)
                    acc[i][j] = fmaf(a[i], b[j], acc[i][j]);
        }
        __syncthreads();
    }

#pragma unroll
    for (int i = 0; i < 8; i++) {
        size_t row = (size_t)(m0 + ty * 8 + i);
#pragma unroll
        for (int j = 0; j < 8; j += 4) {
            int col = n0 + tx * 8 + j;
            float4 r = *(const float4*)(resid + row * 256 + col);
            float4 v = make_float4(fmaf(acc[i][j + 0] + bias[col + 0], st, r.x),
                                   fmaf(acc[i][j + 1] + bias[col + 1], st, r.y),
                                   fmaf(acc[i][j + 2] + bias[col + 2], st, r.z),
                                   fmaf(acc[i][j + 3] + bias[col + 3], st, r.w));
            *(float4*)(out + row * 256 + col) = v;
        }
    }
}

// ---------------- launcher ----------------
extern "C" void kernel_launch(void* const* d_in, const int* in_sizes, int n_in,
                              void* d_out, int out_size)
{
    const float* inputs = (const float*)d_in[0];
    const float* bn1g = (const float*)d_in[1];
    const float* bn1b = (const float*)d_in[2];
    const float* bn1m = (const float*)d_in[3];
    const float* bn1v = (const float*)d_in[4];
    const float* bn2g = (const float*)d_in[5];
    const float* bn2b = (const float*)d_in[6];
    const float* bn2m = (const float*)d_in[7];
    const float* bn2v = (const float*)d_in[8];
    const float* Wg   = (const float*)d_in[9];
    const float* bg   = (const float*)d_in[10];
    const float* Wth  = (const float*)d_in[11];
    const float* bth  = (const float*)d_in[12];
    const float* Wph  = (const float*)d_in[13];
    const float* bph  = (const float*)d_in[14];
    const float* Wz   = (const float*)d_in[15];
    const float* bz   = (const float*)d_in[16];
    const float* sita = (const float*)d_in[17];
    float* out = (float*)d_out;

    float *X, *Y;
    __half *theta, *gfull, *phifull, *phipool, *gT;
    cudaGetSymbolAddress((void**)&X, g_X);
    cudaGetSymbolAddress((void**)&theta, g_theta);
    cudaGetSymbolAddress((void**)&gfull, g_gfull);
    cudaGetSymbolAddress((void**)&phifull, g_phifull);
    cudaGetSymbolAddress((void**)&phipool, g_phipool);
    cudaGetSymbolAddress((void**)&gT, g_gT);
    cudaGetSymbolAddress((void**)&Y, g_Y);

    cudaFuncSetAttribute(k_attn, cudaFuncAttributeMaxDynamicSharedMemorySize, ATTN_SMEM);

    // 1) bn1 + elu
    k_bn1_elu<<<8192, 256>>>((const float4*)inputs, bn1g, bn1b, bn1m, bn1v, (float4*)X);
    // 2) theta / g / phi convs (fp16 outputs)
    k_gemm3<<<dim3(256, 3), 256>>>(X, Wth, bth, theta, Wg, bg, gfull, Wph, bph, phifull);
    // 3) pool (+transpose for g)
    k_pool<<<dim3(32, 8), 256>>>(gfull, phifull, phipool, gT);
    // 4) flash attention (tensor cores, double-buffered, 2 CTA/SM)
    k_attn<<<dim3(32, 8), 256, ATTN_SMEM>>>(theta, phipool, gT, Y);
    // 5) bn2+elu -> W_z -> *sita + residual
    k_gemm_z<<<dim3(256, 2), 256>>>(Y, Wz, bz, bn2g, bn2b, bn2m, bn2v, sita, inputs, out);
}

// round 6
// speedup vs baseline: 8.6106x; 1.8838x over previous
#include <cuda_runtime.h>
#include <cuda_fp16.h>
#include <math.h>

#define EPS 1e-3f

// ---------------- scratch (device globals) ----------------
__device__ __half g_X[8 * 4096 * 256];          // bn1+elu(inputs), fp16
__device__ __half g_theta[8 * 4096 * 128];      // Q, fp16
__device__ __half g_gfull[8 * 4096 * 128];      // g conv out (pre-pool), fp16
__device__ __half g_phifull[8 * 4096 * 128];    // phi conv out (pre-pool), fp16
__device__ __half g_phipool[8 * 2048 * 128];    // K [b][key][ch], fp16
__device__ __half g_gT[8 * 128 * 2048];         // V transposed [b][ch][key], fp16
__device__ __half g_Y[8 * 4096 * 128];          // attention out, fp16
__device__ __half g_WT[3 * 128 * 256];          // W_theta/W_g/W_phi transposed [n][k] fp16
__device__ __half g_WzT[256 * 128];             // W_z transposed [n][k] fp16

__device__ __forceinline__ float elu_f(float v) { return v > 0.f ? v : expm1f(v); }

__device__ __forceinline__ unsigned sptr(const void* p) {
    return (unsigned)__cvta_generic_to_shared(p);
}

__device__ __forceinline__ void mma16816(float* c, const unsigned* a, unsigned b0, unsigned b1) {
    asm volatile(
        "mma.sync.aligned.m16n8k16.row.col.f32.f16.f16.f32 "
        "{%0,%1,%2,%3}, {%4,%5,%6,%7}, {%8,%9}, {%0,%1,%2,%3};"
        : "+f"(c[0]), "+f"(c[1]), "+f"(c[2]), "+f"(c[3])
        : "r"(a[0]), "r"(a[1]), "r"(a[2]), "r"(a[3]), "r"(b0), "r"(b1));
}

__device__ __forceinline__ void mma16816_h(unsigned* c, const unsigned* a, unsigned b0, unsigned b1) {
    asm volatile(
        "mma.sync.aligned.m16n8k16.row.col.f16.f16.f16.f16 "
        "{%0,%1}, {%2,%3,%4,%5}, {%6,%7}, {%0,%1};"
        : "+r"(c[0]), "+r"(c[1])
        : "r"(a[0]), "r"(a[1]), "r"(a[2]), "r"(a[3]), "r"(b0), "r"(b1));
}

// ---------------- kernel 0: weight prep (fp32 -> fp16 transposed [n][k]) ----------------
__global__ void __launch_bounds__(256) k_wprep(
    const float* __restrict__ Wth, const float* __restrict__ Wg, const float* __restrict__ Wph,
    const float* __restrict__ Wz, __half* __restrict__ WT, __half* __restrict__ WzT)
{
    int idx = blockIdx.x * 256 + threadIdx.x;   // 512*256 = 131072
    if (idx < 98304) {
        int m = idx >> 15;          // matrix 0..2
        int r = idx & 32767;
        int n = r >> 8, k = r & 255;
        const float* W = (m == 0) ? Wth : (m == 1) ? Wg : Wph;
        WT[idx] = __float2half(W[k * 128 + n]);
    } else {
        int r = idx - 98304;
        int n = r >> 7, k = r & 127;
        WzT[r] = __float2half(Wz[k * 256 + n]);
    }
}

// ---------------- kernel 1: x = elu(bn1(inputs)), fp16 out ----------------
__global__ void __launch_bounds__(256) k_bn1_elu(
    const float4* __restrict__ in,
    const float* __restrict__ gamma, const float* __restrict__ beta,
    const float* __restrict__ mean, const float* __restrict__ var,
    __half* __restrict__ X)
{
    int i = blockIdx.x * 256 + threadIdx.x;
    int c = (i & 63) * 4;
    float4 v = in[i];
    float ox = elu_f(fmaf(v.x - mean[c + 0], gamma[c + 0] * rsqrtf(var[c + 0] + EPS), beta[c + 0]));
    float oy = elu_f(fmaf(v.y - mean[c + 1], gamma[c + 1] * rsqrtf(var[c + 1] + EPS), beta[c + 1]));
    float oz = elu_f(fmaf(v.z - mean[c + 2], gamma[c + 2] * rsqrtf(var[c + 2] + EPS), beta[c + 2]));
    float ow = elu_f(fmaf(v.w - mean[c + 3], gamma[c + 3] * rsqrtf(var[c + 3] + EPS), beta[c + 3]));
    __half2 h0 = __floats2half2_rn(ox, oy);
    __half2 h1 = __floats2half2_rn(oz, ow);
    uint2 u; u.x = *(unsigned*)&h0; u.y = *(unsigned*)&h1;
    *(uint2*)(X + (size_t)i * 4) = u;
}

// ---------------- kernel 2: three 1x1 convs, fp16 tensor GEMM [32768,256]x[256,128] ----------------
// block 256 (8 warps), tile 128 rows x 128 cols, K chunks of 64, double-buffered cp.async.
#define G3_STAGE 18432   // halves per stage: As 128*72 + Ws 128*72
#define G3_SMEM (2 * G3_STAGE * 2)
__global__ void __launch_bounds__(256, 2) k_gemm3_tc(
    const __half* __restrict__ X, const __half* __restrict__ WTall,
    const float* __restrict__ b0p, const float* __restrict__ b1p, const float* __restrict__ b2p,
    __half* __restrict__ C0, __half* __restrict__ C1, __half* __restrict__ C2)
{
    extern __shared__ __half sm[];
    const __half* WT; const float* bias; __half* C;
    if (blockIdx.y == 0)      { WT = WTall;               bias = b0p; C = C0; }
    else if (blockIdx.y == 1) { WT = WTall + 32768;       bias = b1p; C = C1; }
    else                      { WT = WTall + 65536;       bias = b2p; C = C2; }

    int m0 = blockIdx.x * 128;
    int tid = threadIdx.x;
    int w = tid >> 5, l = tid & 31;
    int g = l >> 2, t = l & 3;

    // stage fill: As[128][72] from X[m0+r][kc*64 + c8]; Ws[128][72] from WT[n][kc*64+c8]
    auto issue = [&](int stg, int kc) {
        __half* As = sm + stg * G3_STAGE;
        __half* Ws = As + 9216;
#pragma unroll
        for (int u = 0; u < 4; u++) {
            int i = tid + u * 256;
            int r = i >> 3, c8 = (i & 7) * 8;
            asm volatile("cp.async.cg.shared.global [%0], [%1], 16;\n"
                         :: "r"(sptr(As + r * 72 + c8)), "l"(X + (size_t)(m0 + r) * 256 + kc * 64 + c8));
        }
#pragma unroll
        for (int u = 0; u < 4; u++) {
            int i = tid + u * 256;
            int n = i >> 3, c8 = (i & 7) * 8;
            asm volatile("cp.async.cg.shared.global [%0], [%1], 16;\n"
                         :: "r"(sptr(Ws + n * 72 + c8)), "l"(WT + n * 256 + kc * 64 + c8));
        }
    };

    float c[16][4];
#pragma unroll
    for (int j = 0; j < 16; j++)
#pragma unroll
        for (int q = 0; q < 4; q++) c[j][q] = 0.f;

    issue(0, 0);
    asm volatile("cp.async.commit_group;\n");

    for (int kc = 0; kc < 4; ++kc) {
        int cur = kc & 1;
        if (kc < 3) {
            issue(cur ^ 1, kc + 1);
            asm volatile("cp.async.commit_group;\n");
            asm volatile("cp.async.wait_group 1;\n");
        } else {
            asm volatile("cp.async.wait_group 0;\n");
        }
        __syncthreads();
        const __half* As = sm + cur * G3_STAGE;
        const __half* Ws = As + 9216;
        int arow = w * 16 + g;
#pragma unroll
        for (int s = 0; s < 4; s++) {
            unsigned a[4];
            a[0] = *(const unsigned*)(As + arow * 72 + s * 16 + 2 * t);
            a[1] = *(const unsigned*)(As + (arow + 8) * 72 + s * 16 + 2 * t);
            a[2] = *(const unsigned*)(As + arow * 72 + s * 16 + 8 + 2 * t);
            a[3] = *(const unsigned*)(As + (arow + 8) * 72 + s * 16 + 8 + 2 * t);
#pragma unroll
            for (int j = 0; j < 16; j++) {
                unsigned bb0 = *(const unsigned*)(Ws + (8 * j + g) * 72 + s * 16 + 2 * t);
                unsigned bb1 = *(const unsigned*)(Ws + (8 * j + g) * 72 + s * 16 + 8 + 2 * t);
                mma16816(c[j], a, bb0, bb1);
            }
        }
        __syncthreads();
    }

    int row = m0 + w * 16 + g;
#pragma unroll
    for (int j = 0; j < 16; j++) {
        int col = j * 8 + 2 * t;
        float bx = bias[col], by = bias[col + 1];
        __half2 h0 = __floats2half2_rn(c[j][0] + bx, c[j][1] + by);
        __half2 h1 = __floats2half2_rn(c[j][2] + bx, c[j][3] + by);
        *(__half2*)(C + (size_t)row * 128 + col) = h0;
        *(__half2*)(C + (size_t)(row + 8) * 128 + col) = h1;
    }
}

// ---------------- kernel 3: pool (w2) for phi -> [key][ch]; pool+transpose for g -> [ch][key] ----------------
#define GP 136
__global__ void __launch_bounds__(256) k_pool(
    const __half* __restrict__ gfull, const __half* __restrict__ phifull,
    __half* __restrict__ phipool, __half* __restrict__ gT)
{
    __shared__ __half Gs[64 * GP];
    int b = blockIdx.y, k0 = blockIdx.x * 64;
    int tid = threadIdx.x;

    union H8 { float4 f; __half2 h[4]; };

    for (int i = tid; i < 64 * 16; i += 256) {
        int r = i >> 4, c8 = (i & 15) * 8;
        int key = k0 + r;
        int h = key >> 5, w2 = key & 31;
        size_t p0 = ((size_t)b * 4096 + (h * 64 + 2 * w2)) * 128 + c8;
        H8 a, c, res;
        a.f = *(const float4*)(gfull + p0);
        c.f = *(const float4*)(gfull + p0 + 128);
#pragma unroll
        for (int k = 0; k < 4; k++) res.h[k] = __hmax2(a.h[k], c.h[k]);
        *(float4*)(Gs + r * GP + c8) = res.f;
        a.f = *(const float4*)(phifull + p0);
        c.f = *(const float4*)(phifull + p0 + 128);
#pragma unroll
        for (int k = 0; k < 4; k++) res.h[k] = __hmax2(a.h[k], c.h[k]);
        *(float4*)(phipool + ((size_t)b * 2048 + key) * 128 + c8) = res.f;
    }
    __syncthreads();

    if (tid < 128) {
        int ch = tid;
        __half tmp[64];
#pragma unroll
        for (int k = 0; k < 64; k++) tmp[k] = Gs[k * GP + ch];
        float4* dst = (float4*)(gT + ((size_t)(b * 128 + ch)) * 2048 + k0);
        const float4* src = (const float4*)tmp;
#pragma unroll
        for (int i = 0; i < 8; i++) dst[i] = src[i];
    }
}

// ---------------- kernel 4: flash attention, fp16 mma, cp.async double buffer ----------------
#define STAGE_H 17920
#define KOFF 0
#define GOFF 8704
#define ATTN_SMEM (2 * STAGE_H * 2)

__device__ __forceinline__ unsigned ex2h2(float a, float b) {
    __half2 h = __floats2half2_rn(a, b);
    unsigned r;
    asm("ex2.approx.f16x2 %0, %1;" : "=r"(r) : "r"(*(unsigned*)&h));
    return r;
}

__device__ __forceinline__ void issue_stage(__half* sm, int stg, int kt, int tid,
                                            const __half* Kg, const __half* Gg)
{
    __half* Kd = sm + stg * STAGE_H + KOFF;
    __half* Gd = sm + stg * STAGE_H + GOFF;
    const __half* Kt = Kg + (size_t)kt * 64 * 128;
    const __half* Gt = Gg + kt * 64;
#pragma unroll
    for (int u = 0; u < 4; u++) {
        int i = tid + u * 256;
        int r = i >> 4, c8 = (i & 15) * 8;
        asm volatile("cp.async.cg.shared.global [%0], [%1], 16;\n"
                     :: "r"(sptr(Kd + r * 136 + c8)), "l"(Kt + r * 128 + c8));
    }
#pragma unroll
    for (int u = 0; u < 4; u++) {
        int i = tid + u * 256;
        int ch = i >> 3, c8 = (i & 7) * 8;
        asm volatile("cp.async.cg.shared.global [%0], [%1], 16;\n"
                     :: "r"(sptr(Gd + ch * 72 + c8)), "l"(Gt + (size_t)ch * 2048 + c8));
    }
}

__global__ void __launch_bounds__(256, 2) k_attn(
    const __half* __restrict__ theta, const __half* __restrict__ phiK,
    const __half* __restrict__ gT, __half* __restrict__ Y)
{
    extern __shared__ __half sm[];

    int b = blockIdx.y, qt = blockIdx.x;
    int tid = threadIdx.x;
    int w = tid >> 5, l = tid & 31;
    int g = l >> 2, t = l & 3;
    const float L2E = 1.4426950408889634f;

    const __half* Qg = theta + ((size_t)b * 4096 + qt * 128) * 128;
    for (int i = tid; i < 128 * 16; i += 256) {
        int r = i >> 4, c8 = (i & 15) * 8;
        *(float4*)(sm + r * 136 + c8) = *(const float4*)(Qg + r * 128 + c8);
    }
    __syncthreads();

    unsigned a_q[8][4];
    int qrow = w * 16 + g;
#pragma unroll
    for (int s = 0; s < 8; s++) {
        a_q[s][0] = *(const unsigned*)(sm + qrow * 136 + s * 16 + 2 * t);
        a_q[s][1] = *(const unsigned*)(sm + (qrow + 8) * 136 + s * 16 + 2 * t);
        a_q[s][2] = *(const unsigned*)(sm + qrow * 136 + s * 16 + 8 + 2 * t);
        a_q[s][3] = *(const unsigned*)(sm + (qrow + 8) * 136 + s * 16 + 8 + 2 * t);
    }
    __syncthreads();

    const __half* Kg = phiK + (size_t)b * 2048 * 128;
    const __half* Gg = gT + (size_t)b * 128 * 2048;

    unsigned oh[16][2];
#pragma unroll
    for (int j = 0; j < 16; j++) { oh[j][0] = 0u; oh[j][1] = 0u; }
    float m0r = -1e30f, m1r = -1e30f, l0 = 0.f, l1 = 0.f;

    issue_stage(sm, 0, 0, tid, Kg, Gg);
    asm volatile("cp.async.commit_group;\n");

    for (int kt = 0; kt < 32; ++kt) {
        int cur = kt & 1;
        if (kt < 31) {
            issue_stage(sm, cur ^ 1, kt + 1, tid, Kg, Gg);
            asm volatile("cp.async.commit_group;\n");
            asm volatile("cp.async.wait_group 1;\n");
        } else {
            asm volatile("cp.async.wait_group 0;\n");
        }
        __syncthreads();

        const __half* Ks = sm + cur * STAGE_H + KOFF;
        const __half* Gs = sm + cur * STAGE_H + GOFF;

        float c[8][4];
#pragma unroll
        for (int j = 0; j < 8; j++)
#pragma unroll
            for (int q = 0; q < 4; q++) c[j][q] = 0.f;
#pragma unroll
        for (int s = 0; s < 8; s++) {
#pragma unroll
            for (int j = 0; j < 8; j++) {
                unsigned b0 = *(const unsigned*)(Ks + (8 * j + g) * 136 + s * 16 + 2 * t);
                unsigned b1 = *(const unsigned*)(Ks + (8 * j + g) * 136 + s * 16 + 8 + 2 * t);
                mma16816(c[j], a_q[s], b0, b1);
            }
        }

        float rmax0 = -1e30f, rmax1 = -1e30f;
#pragma unroll
        for (int j = 0; j < 8; j++) {
            rmax0 = fmaxf(rmax0, fmaxf(c[j][0], c[j][1]));
            rmax1 = fmaxf(rmax1, fmaxf(c[j][2], c[j][3]));
        }
        rmax0 = fmaxf(rmax0, __shfl_xor_sync(0xffffffffu, rmax0, 1));
        rmax0 = fmaxf(rmax0, __shfl_xor_sync(0xffffffffu, rmax0, 2));
        rmax1 = fmaxf(rmax1, __shfl_xor_sync(0xffffffffu, rmax1, 1));
        rmax1 = fmaxf(rmax1, __shfl_xor_sync(0xffffffffu, rmax1, 2));
        float mn0 = fmaxf(m0r, rmax0), mn1 = fmaxf(m1r, rmax1);
        float al0 = __expf(m0r - mn0), al1 = __expf(m1r - mn1);
        m0r = mn0; m1r = mn1;
        float mb0 = mn0 * L2E, mb1 = mn1 * L2E;

        unsigned P0[8], P1[8];
        __half2 ps0 = __float2half2_rn(0.f), ps1 = __float2half2_rn(0.f);
#pragma unroll
        for (int j = 0; j < 8; j++) {
            P0[j] = ex2h2(fmaf(c[j][0], L2E, -mb0), fmaf(c[j][1], L2E, -mb0));
            P1[j] = ex2h2(fmaf(c[j][2], L2E, -mb1), fmaf(c[j][3], L2E, -mb1));
            ps0 = __hadd2(ps0, *(__half2*)&P0[j]);
            ps1 = __hadd2(ps1, *(__half2*)&P1[j]);
        }
        float s0 = __low2float(ps0) + __high2float(ps0);
        float s1 = __low2float(ps1) + __high2float(ps1);
        s0 += __shfl_xor_sync(0xffffffffu, s0, 1);
        s0 += __shfl_xor_sync(0xffffffffu, s0, 2);
        s1 += __shfl_xor_sync(0xffffffffu, s1, 1);
        s1 += __shfl_xor_sync(0xffffffffu, s1, 2);
        l0 = l0 * al0 + s0;
        l1 = l1 * al1 + s1;

        __half2 al0h = __float2half2_rn(al0), al1h = __float2half2_rn(al1);
#pragma unroll
        for (int j = 0; j < 16; j++) {
            *(__half2*)&oh[j][0] = __hmul2(*(__half2*)&oh[j][0], al0h);
            *(__half2*)&oh[j][1] = __hmul2(*(__half2*)&oh[j][1], al1h);
        }

#pragma unroll
        for (int s = 0; s < 4; s++) {
            unsigned pa[4] = { P0[2 * s], P1[2 * s], P0[2 * s + 1], P1[2 * s + 1] };
#pragma unroll
            for (int j = 0; j < 16; j++) {
                unsigned b0 = *(const unsigned*)(Gs + (8 * j + g) * 72 + s * 16 + 2 * t);
                unsigned b1 = *(const unsigned*)(Gs + (8 * j + g) * 72 + s * 16 + 8 + 2 * t);
                mma16816_h(oh[j], pa, b0, b1);
            }
        }
        __syncthreads();
    }

    float inv0 = 1.f / l0, inv1 = 1.f / l1;
    __half2 i0 = __float2half2_rn(inv0), i1 = __float2half2_rn(inv1);
    size_t base = (size_t)b * 4096 + qt * 128 + w * 16;
#pragma unroll
    for (int j = 0; j < 16; j++) {
        __half2 v0 = __hmul2(*(__half2*)&oh[j][0], i0);
        __half2 v1 = __hmul2(*(__half2*)&oh[j][1], i1);
        *(__half2*)(Y + (base + g) * 128 + j * 8 + 2 * t) = v0;
        *(__half2*)(Y + (base + g + 8) * 128 + j * 8 + 2 * t) = v1;
    }
}

// ---------------- kernel 5: out = elu(bn2(Y)) @ W_z + b_z, *sita + inputs (tensor core) ----------------
// block 256 (8 warps), tile 128 rows x 128 cols (grid.y=2 halves of N=256), K=128 resident.
#define GZ_SMEM (1024 + 2 * 128 * 136 * 2)
__global__ void __launch_bounds__(256, 2) k_gemm_z_tc(
    const __half* __restrict__ Yh, const __half* __restrict__ WzT,
    const float* __restrict__ bz,
    const float* __restrict__ g2, const float* __restrict__ b2,
    const float* __restrict__ m2, const float* __restrict__ v2,
    const float* __restrict__ sita, const float* __restrict__ resid, float* __restrict__ out)
{
    extern __shared__ char smz[];
    float* bnS = (float*)smz;                  // [128]
    float* bnH = bnS + 128;                    // [128]
    __half* As = (__half*)(bnH + 128);         // [128][136]
    __half* Ws = As + 128 * 136;               // [128][136]

    int m0 = blockIdx.x * 128;
    int n0 = blockIdx.y * 128;
    int tid = threadIdx.x;
    int w = tid >> 5, l = tid & 31;
    int g = l >> 2, t = l & 3;

    if (tid < 128) {
        float s = g2[tid] * rsqrtf(v2[tid] + EPS);
        bnS[tid] = s;
        bnH[tid] = b2[tid] - m2[tid] * s;
    }
    __syncthreads();

    // A fill: elu(bn2(Y)) -> fp16
    for (int i = tid; i < 128 * 16; i += 256) {
        int r = i >> 4, c8 = (i & 15) * 8;
        uint4 u = *(const uint4*)(Yh + (size_t)(m0 + r) * 128 + c8);
        __half2* hp = (__half2*)&u;
        uint4 o;
        __half2* op = (__half2*)&o;
#pragma unroll
        for (int k = 0; k < 4; k++) {
            float2 f = __half22float2(hp[k]);
            int c = c8 + 2 * k;
            f.x = elu_f(fmaf(f.x, bnS[c], bnH[c]));
            f.y = elu_f(fmaf(f.y, bnS[c + 1], bnH[c + 1]));
            op[k] = __floats2half2_rn(f.x, f.y);
        }
        *(uint4*)(As + r * 136 + c8) = o;
    }
    // W fill
    for (int i = tid; i < 128 * 16; i += 256) {
        int n = i >> 4, c8 = (i & 15) * 8;
        *(uint4*)(Ws + n * 136 + c8) = *(const uint4*)(WzT + (size_t)(n0 + n) * 128 + c8);
    }
    __syncthreads();

    float c[16][4];
#pragma unroll
    for (int j = 0; j < 16; j++)
#pragma unroll
        for (int q = 0; q < 4; q++) c[j][q] = 0.f;

    int arow = w * 16 + g;
#pragma unroll
    for (int s = 0; s < 8; s++) {
        unsigned a[4];
        a[0] = *(const unsigned*)(As + arow * 136 + s * 16 + 2 * t);
        a[1] = *(const unsigned*)(As + (arow + 8) * 136 + s * 16 + 2 * t);
        a[2] = *(const unsigned*)(As + arow * 136 + s * 16 + 8 + 2 * t);
        a[3] = *(const unsigned*)(As + (arow + 8) * 136 + s * 16 + 8 + 2 * t);
#pragma unroll
        for (int j = 0; j < 16; j++) {
            unsigned bb0 = *(const unsigned*)(Ws + (8 * j + g) * 136 + s * 16 + 2 * t);
            unsigned bb1 = *(const unsigned*)(Ws + (8 * j + g) * 136 + s * 16 + 8 + 2 * t);
            mma16816(c[j], a, bb0, bb1);
        }
    }

    float st = *sita;
    size_t row = (size_t)(m0 + w * 16 + g);
#pragma unroll
    for (int j = 0; j < 16; j++) {
        int col = n0 + j * 8 + 2 * t;
        float bx = bz[col], by = bz[col + 1];
        float2 r0 = *(const float2*)(resid + row * 256 + col);
        float2 r1 = *(const float2*)(resid + (row + 8) * 256 + col);
        float2 v0 = make_float2(fmaf(c[j][0] + bx, st, r0.x), fmaf(c[j][1] + by, st, r0.y));
        float2 v1 = make_float2(fmaf(c[j][2] + bx, st, r1.x), fmaf(c[j][3] + by, st, r1.y));
        *(float2*)(out + row * 256 + col) = v0;
        *(float2*)(out + (row + 8) * 256 + col) = v1;
    }
}

// ---------------- launcher ----------------
extern "C" void kernel_launch(void* const* d_in, const int* in_sizes, int n_in,
                              void* d_out, int out_size)
{
    const float* inputs = (const float*)d_in[0];
    const float* bn1g = (const float*)d_in[1];
    const float* bn1b = (const float*)d_in[2];
    const float* bn1m = (const float*)d_in[3];
    const float* bn1v = (const float*)d_in[4];
    const float* bn2g = (const float*)d_in[5];
    const float* bn2b = (const float*)d_in[6];
    const float* bn2m = (const float*)d_in[7];
    const float* bn2v = (const float*)d_in[8];
    const float* Wg   = (const float*)d_in[9];
    const float* bg   = (const float*)d_in[10];
    const float* Wth  = (const float*)d_in[11];
    const float* bth  = (const float*)d_in[12];
    const float* Wph  = (const float*)d_in[13];
    const float* bph  = (const float*)d_in[14];
    const float* Wz   = (const float*)d_in[15];
    const float* bz   = (const float*)d_in[16];
    const float* sita = (const float*)d_in[17];
    float* out = (float*)d_out;

    __half *X, *theta, *gfull, *phifull, *phipool, *gT, *Y, *WT, *WzT;
    cudaGetSymbolAddress((void**)&X, g_X);
    cudaGetSymbolAddress((void**)&theta, g_theta);
    cudaGetSymbolAddress((void**)&gfull, g_gfull);
    cudaGetSymbolAddress((void**)&phifull, g_phifull);
    cudaGetSymbolAddress((void**)&phipool, g_phipool);
    cudaGetSymbolAddress((void**)&gT, g_gT);
    cudaGetSymbolAddress((void**)&Y, g_Y);
    cudaGetSymbolAddress((void**)&WT, g_WT);
    cudaGetSymbolAddress((void**)&WzT, g_WzT);

    cudaFuncSetAttribute(k_attn, cudaFuncAttributeMaxDynamicSharedMemorySize, ATTN_SMEM);
    cudaFuncSetAttribute(k_gemm3_tc, cudaFuncAttributeMaxDynamicSharedMemorySize, G3_SMEM);
    cudaFuncSetAttribute(k_gemm_z_tc, cudaFuncAttributeMaxDynamicSharedMemorySize, GZ_SMEM);

    // 0) weight prep
    k_wprep<<<512, 256>>>(Wth, Wg, Wph, Wz, WT, WzT);
    // 1) bn1 + elu (fp16 out)
    k_bn1_elu<<<8192, 256>>>((const float4*)inputs, bn1g, bn1b, bn1m, bn1v, X);
    // 2) theta / g / phi convs (tensor core)
    k_gemm3_tc<<<dim3(256, 3), 256, G3_SMEM>>>(X, WT, bth, bg, bph, theta, gfull, phifull);
    // 3) pool (+transpose for g)
    k_pool<<<dim3(32, 8), 256>>>(gfull, phifull, phipool, gT);
    // 4) flash attention
    k_attn<<<dim3(32, 8), 256, ATTN_SMEM>>>(theta, phipool, gT, Y);
    // 5) bn2+elu -> W_z -> *sita + residual (tensor core)
    k_gemm_z_tc<<<dim3(256, 2), 256, GZ_SMEM>>>(Y, WzT, bz, bn2g, bn2b, bn2m, bn2v, sita, inputs, out);
}

// round 7
// speedup vs baseline: 9.7001x; 1.1265x over previous
#include <cuda_runtime.h>
#include <cuda_fp16.h>
#include <math.h>

#define EPS 1e-3f

// ---------------- scratch (device globals) ----------------
__device__ __half g_X[8 * 4096 * 256];          // bn1+elu(inputs), fp16
__device__ __half g_theta[8 * 4096 * 128];      // Q, fp16
__device__ __half g_phipool[8 * 2048 * 128];    // K [b][key][ch], fp16
__device__ __half g_gT[8 * 128 * 2048];         // V transposed [b][ch][key], fp16
__device__ __half g_Y[8 * 4096 * 128];          // attention out, fp16
__device__ __half g_WT[3 * 128 * 256];          // W_theta/W_g/W_phi transposed [n][k] fp16
__device__ __half g_WzT[256 * 128];             // W_z transposed [n][k] fp16

__device__ __forceinline__ float elu_f(float v) { return v > 0.f ? v : expm1f(v); }

__device__ __forceinline__ unsigned sptr(const void* p) {
    return (unsigned)__cvta_generic_to_shared(p);
}

__device__ __forceinline__ void mma16816(float* c, const unsigned* a, unsigned b0, unsigned b1) {
    asm volatile(
        "mma.sync.aligned.m16n8k16.row.col.f32.f16.f16.f32 "
        "{%0,%1,%2,%3}, {%4,%5,%6,%7}, {%8,%9}, {%0,%1,%2,%3};"
        : "+f"(c[0]), "+f"(c[1]), "+f"(c[2]), "+f"(c[3])
        : "r"(a[0]), "r"(a[1]), "r"(a[2]), "r"(a[3]), "r"(b0), "r"(b1));
}

__device__ __forceinline__ void mma16816_h(unsigned* c, const unsigned* a, unsigned b0, unsigned b1) {
    asm volatile(
        "mma.sync.aligned.m16n8k16.row.col.f16.f16.f16.f16 "
        "{%0,%1}, {%2,%3,%4,%5}, {%6,%7}, {%0,%1};"
        : "+r"(c[0]), "+r"(c[1])
        : "r"(a[0]), "r"(a[1]), "r"(a[2]), "r"(a[3]), "r"(b0), "r"(b1));
}

__device__ __forceinline__ void ldsm4(unsigned* r, unsigned addr) {
    asm volatile("ldmatrix.sync.aligned.m8n8.x4.shared.b16 {%0,%1,%2,%3}, [%4];"
                 : "=r"(r[0]), "=r"(r[1]), "=r"(r[2]), "=r"(r[3]) : "r"(addr));
}

__device__ __forceinline__ unsigned ex2h2x(unsigned x) {
    unsigned r; asm("ex2.approx.f16x2 %0, %1;" : "=r"(r) : "r"(x)); return r;
}

// ---------------- kernel 0: weight prep (fp32 -> fp16 transposed [n][k]) ----------------
__global__ void __launch_bounds__(256) k_wprep(
    const float* __restrict__ Wth, const float* __restrict__ Wg, const float* __restrict__ Wph,
    const float* __restrict__ Wz, __half* __restrict__ WT, __half* __restrict__ WzT)
{
    int idx = blockIdx.x * 256 + threadIdx.x;   // 512*256 = 131072
    if (idx < 98304) {
        int m = idx >> 15;
        int r = idx & 32767;
        int n = r >> 8, k = r & 255;
        const float* W = (m == 0) ? Wth : (m == 1) ? Wg : Wph;
        WT[idx] = __float2half(W[k * 128 + n]);
    } else {
        int r = idx - 98304;
        int n = r >> 7, k = r & 127;
        WzT[r] = __float2half(Wz[k * 256 + n]);
    }
}

// ---------------- kernel 1: x = elu(bn1(inputs)), fp16 out ----------------
__global__ void __launch_bounds__(256) k_bn1_elu(
    const float4* __restrict__ in,
    const float* __restrict__ gamma, const float* __restrict__ beta,
    const float* __restrict__ mean, const float* __restrict__ var,
    __half* __restrict__ X)
{
    int i = blockIdx.x * 256 + threadIdx.x;
    int c = (i & 63) * 4;
    float4 v = in[i];
    float ox = elu_f(fmaf(v.x - mean[c + 0], gamma[c + 0] * rsqrtf(var[c + 0] + EPS), beta[c + 0]));
    float oy = elu_f(fmaf(v.y - mean[c + 1], gamma[c + 1] * rsqrtf(var[c + 1] + EPS), beta[c + 1]));
    float oz = elu_f(fmaf(v.z - mean[c + 2], gamma[c + 2] * rsqrtf(var[c + 2] + EPS), beta[c + 2]));
    float ow = elu_f(fmaf(v.w - mean[c + 3], gamma[c + 3] * rsqrtf(var[c + 3] + EPS), beta[c + 3]));
    __half2 h0 = __floats2half2_rn(ox, oy);
    __half2 h1 = __floats2half2_rn(oz, ow);
    uint2 u; u.x = *(unsigned*)&h0; u.y = *(unsigned*)&h1;
    *(uint2*)(X + (size_t)i * 4) = u;
}

// ---------------- kernel 2: three 1x1 convs, fp16 tensor GEMM + fused pool/transpose ----------------
// block 256 (8 warps), tile 128 rows x 128 cols, K chunks of 64, double-buffered cp.async.
// y==0: theta -> direct store. y==1: g -> pooled+transposed into gT. y==2: phi -> pooled into phipool.
#define G3_STAGE 18432   // halves per stage: As 128*72 + Ws 128*72
#define G3_SMEM (2 * G3_STAGE * 2)
__global__ void __launch_bounds__(256, 2) k_gemm3_tc(
    const __half* __restrict__ X, const __half* __restrict__ WTall,
    const float* __restrict__ b0p, const float* __restrict__ b1p, const float* __restrict__ b2p,
    __half* __restrict__ theta, __half* __restrict__ gT, __half* __restrict__ phipool)
{
    extern __shared__ __half sm[];
    const __half* WT; const float* bias;
    if (blockIdx.y == 0)      { WT = WTall;         bias = b0p; }
    else if (blockIdx.y == 1) { WT = WTall + 32768; bias = b1p; }
    else                      { WT = WTall + 65536; bias = b2p; }

    int m0 = blockIdx.x * 128;
    int tid = threadIdx.x;
    int w = tid >> 5, l = tid & 31;
    int g = l >> 2, t = l & 3;

    auto issue = [&](int stg, int kc) {
        __half* As = sm + stg * G3_STAGE;
        __half* Ws = As + 9216;
#pragma unroll
        for (int u = 0; u < 4; u++) {
            int i = tid + u * 256;
            int r = i >> 3, c8 = (i & 7) * 8;
            asm volatile("cp.async.cg.shared.global [%0], [%1], 16;\n"
                         :: "r"(sptr(As + r * 72 + c8)), "l"(X + (size_t)(m0 + r) * 256 + kc * 64 + c8));
        }
#pragma unroll
        for (int u = 0; u < 4; u++) {
            int i = tid + u * 256;
            int n = i >> 3, c8 = (i & 7) * 8;
            asm volatile("cp.async.cg.shared.global [%0], [%1], 16;\n"
                         :: "r"(sptr(Ws + n * 72 + c8)), "l"(WT + n * 256 + kc * 64 + c8));
        }
    };

    float c[16][4];
#pragma unroll
    for (int j = 0; j < 16; j++)
#pragma unroll
        for (int q = 0; q < 4; q++) c[j][q] = 0.f;

    issue(0, 0);
    asm volatile("cp.async.commit_group;\n");

    for (int kc = 0; kc < 4; ++kc) {
        int cur = kc & 1;
        asm volatile("cp.async.wait_group 0;\n");
        __syncthreads();
        if (kc < 3) {
            issue(cur ^ 1, kc + 1);
            asm volatile("cp.async.commit_group;\n");
        }
        const __half* As = sm + cur * G3_STAGE;
        const __half* Ws = As + 9216;
        int arow = w * 16 + g;
#pragma unroll
        for (int s = 0; s < 4; s++) {
            unsigned a[4];
            a[0] = *(const unsigned*)(As + arow * 72 + s * 16 + 2 * t);
            a[1] = *(const unsigned*)(As + (arow + 8) * 72 + s * 16 + 2 * t);
            a[2] = *(const unsigned*)(As + arow * 72 + s * 16 + 8 + 2 * t);
            a[3] = *(const unsigned*)(As + (arow + 8) * 72 + s * 16 + 8 + 2 * t);
#pragma unroll
            for (int j = 0; j < 16; j++) {
                unsigned bb0 = *(const unsigned*)(Ws + (8 * j + g) * 72 + s * 16 + 2 * t);
                unsigned bb1 = *(const unsigned*)(Ws + (8 * j + g) * 72 + s * 16 + 8 + 2 * t);
                mma16816(c[j], a, bb0, bb1);
            }
        }
    }

    if (blockIdx.y == 0) {
        int row = m0 + w * 16 + g;
#pragma unroll
        for (int j = 0; j < 16; j++) {
            int col = j * 8 + 2 * t;
            float bx = bias[col], by = bias[col + 1];
            *(__half2*)(theta + (size_t)row * 128 + col) = __floats2half2_rn(c[j][0] + bx, c[j][1] + by);
            *(__half2*)(theta + (size_t)(row + 8) * 128 + col) = __floats2half2_rn(c[j][2] + bx, c[j][3] + by);
        }
        return;
    }

    // stage result tile into smem (stages are dead after sync)
    __syncthreads();
    __half* Cs = sm;                  // [128][136]
    int row = w * 16 + g;
#pragma unroll
    for (int j = 0; j < 16; j++) {
        int col = j * 8 + 2 * t;
        float bx = bias[col], by = bias[col + 1];
        *(__half2*)(Cs + row * 136 + col) = __floats2half2_rn(c[j][0] + bx, c[j][1] + by);
        *(__half2*)(Cs + (row + 8) * 136 + col) = __floats2half2_rn(c[j][2] + bx, c[j][3] + by);
    }
    __syncthreads();

    int bb = m0 >> 12;
    int key0 = (m0 >> 1) & 2047;

    if (blockIdx.y == 2) {
        // phi: pool width-2 -> phipool[b][key][ch]
        for (int i = tid; i < 64 * 16; i += 256) {
            int r = i >> 4, c8 = (i & 15) * 8;
            uint4 a4 = *(const uint4*)(Cs + (2 * r) * 136 + c8);
            uint4 b4 = *(const uint4*)(Cs + (2 * r + 1) * 136 + c8);
            __half2* ah = (__half2*)&a4;
            __half2* bh = (__half2*)&b4;
            uint4 o;
            __half2* oh = (__half2*)&o;
#pragma unroll
            for (int k = 0; k < 4; k++) oh[k] = __hmax2(ah[k], bh[k]);
            *(uint4*)(phipool + ((size_t)bb * 2048 + key0 + r) * 128 + c8) = o;
        }
    } else {
        // g: pool + transpose -> gT[b][ch][key]
        if (tid < 128) {
            int ch = tid;
            __half tmp[64];
#pragma unroll
            for (int k = 0; k < 64; k++)
                tmp[k] = __hmax(Cs[(2 * k) * 136 + ch], Cs[(2 * k + 1) * 136 + ch]);
            float4* dst = (float4*)(gT + ((size_t)(bb * 128 + ch)) * 2048 + key0);
            const float4* src = (const float4*)tmp;
#pragma unroll
            for (int i = 0; i < 8; i++) dst[i] = src[i];
        }
    }
}

// ---------------- kernel 4: flash attention, fp16 mma + ldmatrix + half2 softmax ----------------
#define STAGE_H 17920
#define KOFF 0
#define GOFF 8704
#define ATTN_SMEM (2 * STAGE_H * 2)

__device__ __forceinline__ void issue_stage(__half* sm, int stg, int kt, int tid,
                                            const __half* Kg, const __half* Gg)
{
    __half* Kd = sm + stg * STAGE_H + KOFF;
    __half* Gd = sm + stg * STAGE_H + GOFF;
    const __half* Kt = Kg + (size_t)kt * 64 * 128;
    const __half* Gt = Gg + kt * 64;
#pragma unroll
    for (int u = 0; u < 4; u++) {
        int i = tid + u * 256;
        int r = i >> 4, c8 = (i & 15) * 8;
        asm volatile("cp.async.cg.shared.global [%0], [%1], 16;\n"
                     :: "r"(sptr(Kd + r * 136 + c8)), "l"(Kt + r * 128 + c8));
    }
#pragma unroll
    for (int u = 0; u < 4; u++) {
        int i = tid + u * 256;
        int ch = i >> 3, c8 = (i & 7) * 8;
        asm volatile("cp.async.cg.shared.global [%0], [%1], 16;\n"
                     :: "r"(sptr(Gd + ch * 72 + c8)), "l"(Gt + (size_t)ch * 2048 + c8));
    }
}

__global__ void __launch_bounds__(256, 2) k_attn(
    const __half* __restrict__ theta, const __half* __restrict__ phiK,
    const __half* __restrict__ gT, __half* __restrict__ Y)
{
    extern __shared__ __half sm[];

    int b = blockIdx.y, qt = blockIdx.x;
    int tid = threadIdx.x;
    int w = tid >> 5, l = tid & 31;
    int g = l >> 2, t = l & 3;
    const float L2E = 1.4426950408889634f;
    const __half2 L2E2 = __float2half2_rn(L2E);

    // ldmatrix lane offsets: B-order (tiles: n+0/k+8/n+8/both), A-order (m+0/m+8/k+8/both)
    int lrowB = (l & 7) + ((l >> 4) << 3);
    int lcolB = ((l >> 3) & 1) * 8;
    int lrowA = (l & 7) + (((l >> 3) & 1) << 3);
    int lcolA = (l >> 4) * 8;

    // --- Q phase ---
    const __half* Qg = theta + ((size_t)b * 4096 + qt * 128) * 128;
    for (int i = tid; i < 128 * 16; i += 256) {
        int r = i >> 4, c8 = (i & 15) * 8;
        *(float4*)(sm + r * 136 + c8) = *(const float4*)(Qg + r * 128 + c8);
    }
    __syncthreads();

    unsigned a_q[8][4];
#pragma unroll
    for (int s = 0; s < 8; s++)
        ldsm4(a_q[s], sptr(sm + (w * 16 + lrowA) * 136 + s * 16 + lcolA));
    __syncthreads();

    const __half* Kg = phiK + (size_t)b * 2048 * 128;
    const __half* Gg = gT + (size_t)b * 128 * 2048;

    unsigned oh[16][2];
#pragma unroll
    for (int j = 0; j < 16; j++) { oh[j][0] = 0u; oh[j][1] = 0u; }
    float m0r = -1e30f, m1r = -1e30f, l0 = 0.f, l1 = 0.f;

    issue_stage(sm, 0, 0, tid, Kg, Gg);
    asm volatile("cp.async.commit_group;\n");

    for (int kt = 0; kt < 32; ++kt) {
        int cur = kt & 1;
        asm volatile("cp.async.wait_group 0;\n");
        __syncthreads();
        if (kt < 31) {
            issue_stage(sm, cur ^ 1, kt + 1, tid, Kg, Gg);
            asm volatile("cp.async.commit_group;\n");
        }

        const __half* Ks = sm + cur * STAGE_H + KOFF;
        const __half* Gs = sm + cur * STAGE_H + GOFF;

        // --- S = Q @ K^T, fp16 accum ---
        unsigned ch2[8][2];
#pragma unroll
        for (int j = 0; j < 8; j++) { ch2[j][0] = 0u; ch2[j][1] = 0u; }
#pragma unroll
        for (int s = 0; s < 8; s++) {
#pragma unroll
            for (int jp = 0; jp < 4; jp++) {
                unsigned bm[4];
                ldsm4(bm, sptr(Ks + (16 * jp + lrowB) * 136 + s * 16 + lcolB));
                mma16816_h(ch2[2 * jp], a_q[s], bm[0], bm[1]);
                mma16816_h(ch2[2 * jp + 1], a_q[s], bm[2], bm[3]);
            }
        }

        // --- softmax (half2) ---
        __half2 hm0 = *(__half2*)&ch2[0][0], hm1 = *(__half2*)&ch2[0][1];
#pragma unroll
        for (int j = 1; j < 8; j++) {
            hm0 = __hmax2(hm0, *(__half2*)&ch2[j][0]);
            hm1 = __hmax2(hm1, *(__half2*)&ch2[j][1]);
        }
        float rmax0 = fmaxf(__low2float(hm0), __high2float(hm0));
        float rmax1 = fmaxf(__low2float(hm1), __high2float(hm1));
        rmax0 = fmaxf(rmax0, __shfl_xor_sync(0xffffffffu, rmax0, 1));
        rmax0 = fmaxf(rmax0, __shfl_xor_sync(0xffffffffu, rmax0, 2));
        rmax1 = fmaxf(rmax1, __shfl_xor_sync(0xffffffffu, rmax1, 1));
        rmax1 = fmaxf(rmax1, __shfl_xor_sync(0xffffffffu, rmax1, 2));
        float mn0 = fmaxf(m0r, rmax0), mn1 = fmaxf(m1r, rmax1);
        float al0 = __expf(m0r - mn0), al1 = __expf(m1r - mn1);
        m0r = mn0; m1r = mn1;
        __half2 nb0 = __float2half2_rn(-mn0 * L2E);
        __half2 nb1 = __float2half2_rn(-mn1 * L2E);

        unsigned P0[8], P1[8];
        float s0 = 0.f, s1 = 0.f;
#pragma unroll
        for (int j = 0; j < 8; j++) {
            __half2 d0 = __hfma2(*(__half2*)&ch2[j][0], L2E2, nb0);
            __half2 d1 = __hfma2(*(__half2*)&ch2[j][1], L2E2, nb1);
            P0[j] = ex2h2x(*(unsigned*)&d0);
            P1[j] = ex2h2x(*(unsigned*)&d1);
            float2 f0 = __half22float2(*(__half2*)&P0[j]);
            float2 f1 = __half22float2(*(__half2*)&P1[j]);
            s0 += f0.x + f0.y;
            s1 += f1.x + f1.y;
        }
        s0 += __shfl_xor_sync(0xffffffffu, s0, 1);
        s0 += __shfl_xor_sync(0xffffffffu, s0, 2);
        s1 += __shfl_xor_sync(0xffffffffu, s1, 1);
        s1 += __shfl_xor_sync(0xffffffffu, s1, 2);
        l0 = l0 * al0 + s0;
        l1 = l1 * al1 + s1;

        __half2 al0h = __float2half2_rn(al0), al1h = __float2half2_rn(al1);
#pragma unroll
        for (int j = 0; j < 16; j++) {
            *(__half2*)&oh[j][0] = __hmul2(*(__half2*)&oh[j][0], al0h);
            *(__half2*)&oh[j][1] = __hmul2(*(__half2*)&oh[j][1], al1h);
        }

        // --- O += P @ G, fp16 accum, ldmatrix B ---
#pragma unroll
        for (int s = 0; s < 4; s++) {
            unsigned pa[4] = { P0[2 * s], P1[2 * s], P0[2 * s + 1], P1[2 * s + 1] };
#pragma unroll
            for (int jp = 0; jp < 8; jp++) {
                unsigned gm[4];
                ldsm4(gm, sptr(Gs + (16 * jp + lrowB) * 72 + s * 16 + lcolB));
                mma16816_h(oh[2 * jp], pa, gm[0], gm[1]);
                mma16816_h(oh[2 * jp + 1], pa, gm[2], gm[3]);
            }
        }
    }

    float inv0 = 1.f / l0, inv1 = 1.f / l1;
    __half2 i0 = __float2half2_rn(inv0), i1 = __float2half2_rn(inv1);
    size_t base = (size_t)b * 4096 + qt * 128 + w * 16;
#pragma unroll
    for (int j = 0; j < 16; j++) {
        __half2 v0 = __hmul2(*(__half2*)&oh[j][0], i0);
        __half2 v1 = __hmul2(*(__half2*)&oh[j][1], i1);
        *(__half2*)(Y + (base + g) * 128 + j * 8 + 2 * t) = v0;
        *(__half2*)(Y + (base + g + 8) * 128 + j * 8 + 2 * t) = v1;
    }
}

// ---------------- kernel 5: out = elu(bn2(Y)) @ W_z + b_z, *sita + inputs (tensor core) ----------------
#define GZ_SMEM (1024 + 2 * 128 * 136 * 2)
__global__ void __launch_bounds__(256, 2) k_gemm_z_tc(
    const __half* __restrict__ Yh, const __half* __restrict__ WzT,
    const float* __restrict__ bz,
    const float* __restrict__ g2, const float* __restrict__ b2,
    const float* __restrict__ m2, const float* __restrict__ v2,
    const float* __restrict__ sita, const float* __restrict__ resid, float* __restrict__ out)
{
    extern __shared__ char smz[];
    float* bnS = (float*)smz;
    float* bnH = bnS + 128;
    __half* As = (__half*)(bnH + 128);
    __half* Ws = As + 128 * 136;

    int m0 = blockIdx.x * 128;
    int n0 = blockIdx.y * 128;
    int tid = threadIdx.x;
    int w = tid >> 5, l = tid & 31;
    int g = l >> 2, t = l & 3;

    if (tid < 128) {
        float s = g2[tid] * rsqrtf(v2[tid] + EPS);
        bnS[tid] = s;
        bnH[tid] = b2[tid] - m2[tid] * s;
    }
    __syncthreads();

    for (int i = tid; i < 128 * 16; i += 256) {
        int r = i >> 4, c8 = (i & 15) * 8;
        uint4 u = *(const uint4*)(Yh + (size_t)(m0 + r) * 128 + c8);
        __half2* hp = (__half2*)&u;
        uint4 o;
        __half2* op = (__half2*)&o;
#pragma unroll
        for (int k = 0; k < 4; k++) {
            float2 f = __half22float2(hp[k]);
            int c = c8 + 2 * k;
            f.x = elu_f(fmaf(f.x, bnS[c], bnH[c]));
            f.y = elu_f(fmaf(f.y, bnS[c + 1], bnH[c + 1]));
            op[k] = __floats2half2_rn(f.x, f.y);
        }
        *(uint4*)(As + r * 136 + c8) = o;
    }
    for (int i = tid; i < 128 * 16; i += 256) {
        int n = i >> 4, c8 = (i & 15) * 8;
        *(uint4*)(Ws + n * 136 + c8) = *(const uint4*)(WzT + (size_t)(n0 + n) * 128 + c8);
    }
    __syncthreads();

    float c[16][4];
#pragma unroll
    for (int j = 0; j < 16; j++)
#pragma unroll
        for (int q = 0; q < 4; q++) c[j][q] = 0.f;

    int arow = w * 16 + g;
#pragma unroll
    for (int s = 0; s < 8; s++) {
        unsigned a[4];
        a[0] = *(const unsigned*)(As + arow * 136 + s * 16 + 2 * t);
        a[1] = *(const unsigned*)(As + (arow + 8) * 136 + s * 16 + 2 * t);
        a[2] = *(const unsigned*)(As + arow * 136 + s * 16 + 8 + 2 * t);
        a[3] = *(const unsigned*)(As + (arow + 8) * 136 + s * 16 + 8 + 2 * t);
#pragma unroll
        for (int j = 0; j < 16; j++) {
            unsigned bb0 = *(const unsigned*)(Ws + (8 * j + g) * 136 + s * 16 + 2 * t);
            unsigned bb1 = *(const unsigned*)(Ws + (8 * j + g) * 136 + s * 16 + 8 + 2 * t);
            mma16816(c[j], a, bb0, bb1);
        }
    }

    float st = *sita;
    size_t row = (size_t)(m0 + w * 16 + g);
#pragma unroll
    for (int j = 0; j < 16; j++) {
        int col = n0 + j * 8 + 2 * t;
        float bx = bz[col], by = bz[col + 1];
        float2 r0 = *(const float2*)(resid + row * 256 + col);
        float2 r1 = *(const float2*)(resid + (row + 8) * 256 + col);
        float2 v0 = make_float2(fmaf(c[j][0] + bx, st, r0.x), fmaf(c[j][1] + by, st, r0.y));
        float2 v1 = make_float2(fmaf(c[j][2] + bx, st, r1.x), fmaf(c[j][3] + by, st, r1.y));
        *(float2*)(out + row * 256 + col) = v0;
        *(float2*)(out + (row + 8) * 256 + col) = v1;
    }
}

// ---------------- launcher ----------------
extern "C" void kernel_launch(void* const* d_in, const int* in_sizes, int n_in,
                              void* d_out, int out_size)
{
    const float* inputs = (const float*)d_in[0];
    const float* bn1g = (const float*)d_in[1];
    const float* bn1b = (const float*)d_in[2];
    const float* bn1m = (const float*)d_in[3];
    const float* bn1v = (const float*)d_in[4];
    const float* bn2g = (const float*)d_in[5];
    const float* bn2b = (const float*)d_in[6];
    const float* bn2m = (const float*)d_in[7];
    const float* bn2v = (const float*)d_in[8];
    const float* Wg   = (const float*)d_in[9];
    const float* bg   = (const float*)d_in[10];
    const float* Wth  = (const float*)d_in[11];
    const float* bth  = (const float*)d_in[12];
    const float* Wph  = (const float*)d_in[13];
    const float* bph  = (const float*)d_in[14];
    const float* Wz   = (const float*)d_in[15];
    const float* bz   = (const float*)d_in[16];
    const float* sita = (const float*)d_in[17];
    float* out = (float*)d_out;

    __half *X, *theta, *phipool, *gT, *Y, *WT, *WzT;
    cudaGetSymbolAddress((void**)&X, g_X);
    cudaGetSymbolAddress((void**)&theta, g_theta);
    cudaGetSymbolAddress((void**)&phipool, g_phipool);
    cudaGetSymbolAddress((void**)&gT, g_gT);
    cudaGetSymbolAddress((void**)&Y, g_Y);
    cudaGetSymbolAddress((void**)&WT, g_WT);
    cudaGetSymbolAddress((void**)&WzT, g_WzT);

    cudaFuncSetAttribute(k_attn, cudaFuncAttributeMaxDynamicSharedMemorySize, ATTN_SMEM);
    cudaFuncSetAttribute(k_gemm3_tc, cudaFuncAttributeMaxDynamicSharedMemorySize, G3_SMEM);
    cudaFuncSetAttribute(k_gemm_z_tc, cudaFuncAttributeMaxDynamicSharedMemorySize, GZ_SMEM);

    // 0) weight prep
    k_wprep<<<512, 256>>>(Wth, Wg, Wph, Wz, WT, WzT);
    // 1) bn1 + elu (fp16 out)
    k_bn1_elu<<<8192, 256>>>((const float4*)inputs, bn1g, bn1b, bn1m, bn1v, X);
    // 2) theta / g / phi convs (tensor core) with fused pool+transpose for g/phi
    k_gemm3_tc<<<dim3(256, 3), 256, G3_SMEM>>>(X, WT, bth, bg, bph, theta, gT, phipool);
    // 3) flash attention
    k_attn<<<dim3(32, 8), 256, ATTN_SMEM>>>(theta, phipool, gT, Y);
    // 4) bn2+elu -> W_z -> *sita + residual (tensor core)
    k_gemm_z_tc<<<dim3(256, 2), 256, GZ_SMEM>>>(Y, WzT, bz, bn2g, bn2b, bn2m, bn2v, sita, inputs, out);
}

// round 8
// speedup vs baseline: 9.9791x; 1.0288x over previous
#include <cuda_runtime.h>
#include <cuda_fp16.h>
#include <math.h>

#define EPS 1e-3f

// ---------------- scratch (device globals) ----------------
__device__ __half g_X[8 * 4096 * 256];          // bn1+elu(inputs), fp16
__device__ __half g_theta[8 * 4096 * 128];      // Q, fp16
__device__ __half g_phipool[8 * 2048 * 128];    // K [b][key][ch], fp16
__device__ __half g_gT[8 * 128 * 2048];         // V transposed [b][ch][key], fp16
__device__ __half g_Y[8 * 4096 * 128];          // attention out, fp16
__device__ __half g_WT[3 * 128 * 256];          // W_theta/W_g/W_phi transposed [n][k] fp16
__device__ __half g_WzT[256 * 128];             // W_z transposed [n][k] fp16

__device__ __forceinline__ float elu_f(float v) { return v > 0.f ? v : expm1f(v); }

__device__ __forceinline__ unsigned sptr(const void* p) {
    return (unsigned)__cvta_generic_to_shared(p);
}

__device__ __forceinline__ void mma16816(float* c, const unsigned* a, unsigned b0, unsigned b1) {
    asm volatile(
        "mma.sync.aligned.m16n8k16.row.col.f32.f16.f16.f32 "
        "{%0,%1,%2,%3}, {%4,%5,%6,%7}, {%8,%9}, {%0,%1,%2,%3};"
        : "+f"(c[0]), "+f"(c[1]), "+f"(c[2]), "+f"(c[3])
        : "r"(a[0]), "r"(a[1]), "r"(a[2]), "r"(a[3]), "r"(b0), "r"(b1));
}

__device__ __forceinline__ void mma16816_h(unsigned* c, const unsigned* a, unsigned b0, unsigned b1) {
    asm volatile(
        "mma.sync.aligned.m16n8k16.row.col.f16.f16.f16.f16 "
        "{%0,%1}, {%2,%3,%4,%5}, {%6,%7}, {%0,%1};"
        : "+r"(c[0]), "+r"(c[1])
        : "r"(a[0]), "r"(a[1]), "r"(a[2]), "r"(a[3]), "r"(b0), "r"(b1));
}

__device__ __forceinline__ void ldsm4(unsigned* r, unsigned addr) {
    asm volatile("ldmatrix.sync.aligned.m8n8.x4.shared.b16 {%0,%1,%2,%3}, [%4];"
                 : "=r"(r[0]), "=r"(r[1]), "=r"(r[2]), "=r"(r[3]) : "r"(addr));
}

__device__ __forceinline__ unsigned ex2h2x(unsigned x) {
    unsigned r; asm("ex2.approx.f16x2 %0, %1;" : "=r"(r) : "r"(x)); return r;
}

// ---------------- kernel 0: weight prep (fp32 -> fp16 transposed [n][k]) ----------------
__global__ void __launch_bounds__(256) k_wprep(
    const float* __restrict__ Wth, const float* __restrict__ Wg, const float* __restrict__ Wph,
    const float* __restrict__ Wz, __half* __restrict__ WT, __half* __restrict__ WzT)
{
    int idx = blockIdx.x * 256 + threadIdx.x;   // 512*256 = 131072
    if (idx < 98304) {
        int m = idx >> 15;
        int r = idx & 32767;
        int n = r >> 8, k = r & 255;
        const float* W = (m == 0) ? Wth : (m == 1) ? Wg : Wph;
        WT[idx] = __float2half(W[k * 128 + n]);
    } else {
        int r = idx - 98304;
        int n = r >> 7, k = r & 127;
        WzT[r] = __float2half(Wz[k * 256 + n]);
    }
}

// ---------------- kernel 1: x = elu(bn1(inputs)), fp16 out ----------------
__global__ void __launch_bounds__(256) k_bn1_elu(
    const float4* __restrict__ in,
    const float* __restrict__ gamma, const float* __restrict__ beta,
    const float* __restrict__ mean, const float* __restrict__ var,
    __half* __restrict__ X)
{
    int i = blockIdx.x * 256 + threadIdx.x;
    int c = (i & 63) * 4;
    float4 v = in[i];
    float ox = elu_f(fmaf(v.x - mean[c + 0], gamma[c + 0] * rsqrtf(var[c + 0] + EPS), beta[c + 0]));
    float oy = elu_f(fmaf(v.y - mean[c + 1], gamma[c + 1] * rsqrtf(var[c + 1] + EPS), beta[c + 1]));
    float oz = elu_f(fmaf(v.z - mean[c + 2], gamma[c + 2] * rsqrtf(var[c + 2] + EPS), beta[c + 2]));
    float ow = elu_f(fmaf(v.w - mean[c + 3], gamma[c + 3] * rsqrtf(var[c + 3] + EPS), beta[c + 3]));
    __half2 h0 = __floats2half2_rn(ox, oy);
    __half2 h1 = __floats2half2_rn(oz, ow);
    uint2 u; u.x = *(unsigned*)&h0; u.y = *(unsigned*)&h1;
    *(uint2*)(X + (size_t)i * 4) = u;
}

// ---------------- kernel 2: three 1x1 convs, fp16 tensor GEMM + fused pool/transpose ----------------
#define G3_STAGE 18432   // halves per stage: As 128*72 + Ws 128*72
#define G3_SMEM (2 * G3_STAGE * 2)
__global__ void __launch_bounds__(256, 2) k_gemm3_tc(
    const __half* __restrict__ X, const __half* __restrict__ WTall,
    const float* __restrict__ b0p, const float* __restrict__ b1p, const float* __restrict__ b2p,
    __half* __restrict__ theta, __half* __restrict__ gT, __half* __restrict__ phipool)
{
    extern __shared__ __half sm[];
    const __half* WT; const float* bias;
    if (blockIdx.y == 0)      { WT = WTall;         bias = b0p; }
    else if (blockIdx.y == 1) { WT = WTall + 32768; bias = b1p; }
    else                      { WT = WTall + 65536; bias = b2p; }

    int m0 = blockIdx.x * 128;
    int tid = threadIdx.x;
    int w = tid >> 5, l = tid & 31;
    int g = l >> 2, t = l & 3;

    auto issue = [&](int stg, int kc) {
        __half* As = sm + stg * G3_STAGE;
        __half* Ws = As + 9216;
#pragma unroll
        for (int u = 0; u < 4; u++) {
            int i = tid + u * 256;
            int r = i >> 3, c8 = (i & 7) * 8;
            asm volatile("cp.async.cg.shared.global [%0], [%1], 16;\n"
                         :: "r"(sptr(As + r * 72 + c8)), "l"(X + (size_t)(m0 + r) * 256 + kc * 64 + c8));
        }
#pragma unroll
        for (int u = 0; u < 4; u++) {
            int i = tid + u * 256;
            int n = i >> 3, c8 = (i & 7) * 8;
            asm volatile("cp.async.cg.shared.global [%0], [%1], 16;\n"
                         :: "r"(sptr(Ws + n * 72 + c8)), "l"(WT + n * 256 + kc * 64 + c8));
        }
    };

    float c[16][4];
#pragma unroll
    for (int j = 0; j < 16; j++)
#pragma unroll
        for (int q = 0; q < 4; q++) c[j][q] = 0.f;

    issue(0, 0);
    asm volatile("cp.async.commit_group;\n");

    for (int kc = 0; kc < 4; ++kc) {
        int cur = kc & 1;
        asm volatile("cp.async.wait_group 0;\n");
        __syncthreads();
        if (kc < 3) {
            issue(cur ^ 1, kc + 1);
            asm volatile("cp.async.commit_group;\n");
        }
        const __half* As = sm + cur * G3_STAGE;
        const __half* Ws = As + 9216;
        int arow = w * 16 + g;
#pragma unroll
        for (int s = 0; s < 4; s++) {
            unsigned a[4];
            a[0] = *(const unsigned*)(As + arow * 72 + s * 16 + 2 * t);
            a[1] = *(const unsigned*)(As + (arow + 8) * 72 + s * 16 + 2 * t);
            a[2] = *(const unsigned*)(As + arow * 72 + s * 16 + 8 + 2 * t);
            a[3] = *(const unsigned*)(As + (arow + 8) * 72 + s * 16 + 8 + 2 * t);
#pragma unroll
            for (int j = 0; j < 16; j++) {
                unsigned bb0 = *(const unsigned*)(Ws + (8 * j + g) * 72 + s * 16 + 2 * t);
                unsigned bb1 = *(const unsigned*)(Ws + (8 * j + g) * 72 + s * 16 + 8 + 2 * t);
                mma16816(c[j], a, bb0, bb1);
            }
        }
    }

    if (blockIdx.y == 0) {
        int row = m0 + w * 16 + g;
#pragma unroll
        for (int j = 0; j < 16; j++) {
            int col = j * 8 + 2 * t;
            float bx = bias[col], by = bias[col + 1];
            *(__half2*)(theta + (size_t)row * 128 + col) = __floats2half2_rn(c[j][0] + bx, c[j][1] + by);
            *(__half2*)(theta + (size_t)(row + 8) * 128 + col) = __floats2half2_rn(c[j][2] + bx, c[j][3] + by);
        }
        return;
    }

    __syncthreads();
    __half* Cs = sm;                  // [128][136]
    int row = w * 16 + g;
#pragma unroll
    for (int j = 0; j < 16; j++) {
        int col = j * 8 + 2 * t;
        float bx = bias[col], by = bias[col + 1];
        *(__half2*)(Cs + row * 136 + col) = __floats2half2_rn(c[j][0] + bx, c[j][1] + by);
        *(__half2*)(Cs + (row + 8) * 136 + col) = __floats2half2_rn(c[j][2] + bx, c[j][3] + by);
    }
    __syncthreads();

    int bb = m0 >> 12;
    int key0 = (m0 >> 1) & 2047;

    if (blockIdx.y == 2) {
        for (int i = tid; i < 64 * 16; i += 256) {
            int r = i >> 4, c8 = (i & 15) * 8;
            uint4 a4 = *(const uint4*)(Cs + (2 * r) * 136 + c8);
            uint4 b4 = *(const uint4*)(Cs + (2 * r + 1) * 136 + c8);
            __half2* ah = (__half2*)&a4;
            __half2* bh = (__half2*)&b4;
            uint4 o;
            __half2* oh = (__half2*)&o;
#pragma unroll
            for (int k = 0; k < 4; k++) oh[k] = __hmax2(ah[k], bh[k]);
            *(uint4*)(phipool + ((size_t)bb * 2048 + key0 + r) * 128 + c8) = o;
        }
    } else {
        if (tid < 128) {
            int ch = tid;
            __half tmp[64];
#pragma unroll
            for (int k = 0; k < 64; k++)
                tmp[k] = __hmax(Cs[(2 * k) * 136 + ch], Cs[(2 * k + 1) * 136 + ch]);
            float4* dst = (float4*)(gT + ((size_t)(bb * 128 + ch)) * 2048 + key0);
            const float4* src = (const float4*)tmp;
#pragma unroll
            for (int i = 0; i < 8; i++) dst[i] = src[i];
        }
    }
}

// ---------------- kernel 4: flash attention — 4 warps x 32 query rows ----------------
#define STAGE_H 17920
#define KOFF 0
#define GOFF 8704
#define ATTN_SMEM (2 * STAGE_H * 2)

__device__ __forceinline__ void issue_stage(__half* sm, int stg, int kt, int tid,
                                            const __half* Kg, const __half* Gg)
{
    __half* Kd = sm + stg * STAGE_H + KOFF;
    __half* Gd = sm + stg * STAGE_H + GOFF;
    const __half* Kt = Kg + (size_t)kt * 64 * 128;
    const __half* Gt = Gg + kt * 64;
#pragma unroll
    for (int u = 0; u < 8; u++) {
        int i = tid + u * 128;               // [0,1024)
        int r = i >> 4, c8 = (i & 15) * 8;
        asm volatile("cp.async.cg.shared.global [%0], [%1], 16;\n"
                     :: "r"(sptr(Kd + r * 136 + c8)), "l"(Kt + r * 128 + c8));
    }
#pragma unroll
    for (int u = 0; u < 8; u++) {
        int i = tid + u * 128;               // [0,1024)
        int ch = i >> 3, c8 = (i & 7) * 8;
        asm volatile("cp.async.cg.shared.global [%0], [%1], 16;\n"
                     :: "r"(sptr(Gd + ch * 72 + c8)), "l"(Gt + (size_t)ch * 2048 + c8));
    }
}

__global__ void __launch_bounds__(128, 2) k_attn(
    const __half* __restrict__ theta, const __half* __restrict__ phiK,
    const __half* __restrict__ gT, __half* __restrict__ Y)
{
    extern __shared__ __half sm[];

    int b = blockIdx.y, qt = blockIdx.x;
    int tid = threadIdx.x;
    int w = tid >> 5, l = tid & 31;
    int g = l >> 2, t = l & 3;
    const float L2E = 1.4426950408889634f;
    const __half2 L2E2 = __float2half2_rn(L2E);

    int lrowB = (l & 7) + ((l >> 4) << 3);
    int lcolB = ((l >> 3) & 1) * 8;
    int lrowA = (l & 7) + (((l >> 3) & 1) << 3);
    int lcolA = (l >> 4) * 8;

    // --- Q phase: warp owns rows [w*32, w*32+32) as two m16 tiles ---
    const __half* Qg = theta + ((size_t)b * 4096 + qt * 128) * 128;
    for (int i = tid; i < 128 * 16; i += 128) {
        int r = i >> 4, c8 = (i & 15) * 8;
        *(float4*)(sm + r * 136 + c8) = *(const float4*)(Qg + r * 128 + c8);
    }
    __syncthreads();

    unsigned a_q[2][8][4];
#pragma unroll
    for (int mt = 0; mt < 2; mt++)
#pragma unroll
        for (int s = 0; s < 8; s++)
            ldsm4(a_q[mt][s], sptr(sm + (w * 32 + mt * 16 + lrowA) * 136 + s * 16 + lcolA));
    __syncthreads();

    const __half* Kg = phiK + (size_t)b * 2048 * 128;
    const __half* Gg = gT + (size_t)b * 128 * 2048;

    unsigned oh[2][16][2];
#pragma unroll
    for (int mt = 0; mt < 2; mt++)
#pragma unroll
        for (int j = 0; j < 16; j++) { oh[mt][j][0] = 0u; oh[mt][j][1] = 0u; }
    float mreg[2][2] = {{-1e30f, -1e30f}, {-1e30f, -1e30f}};
    float lreg[2][2] = {{0.f, 0.f}, {0.f, 0.f}};

    issue_stage(sm, 0, 0, tid, Kg, Gg);
    asm volatile("cp.async.commit_group;\n");

    for (int kt = 0; kt < 32; ++kt) {
        int cur = kt & 1;
        asm volatile("cp.async.wait_group 0;\n");
        __syncthreads();
        if (kt < 31) {
            issue_stage(sm, cur ^ 1, kt + 1, tid, Kg, Gg);
            asm volatile("cp.async.commit_group;\n");
        }

        const __half* Ks = sm + cur * STAGE_H + KOFF;
        const __half* Gs = sm + cur * STAGE_H + GOFF;

        // --- S = Q @ K^T, fp16 accum; each K fragment feeds both m-tiles ---
        unsigned ch2[2][8][2];
#pragma unroll
        for (int mt = 0; mt < 2; mt++)
#pragma unroll
            for (int j = 0; j < 8; j++) { ch2[mt][j][0] = 0u; ch2[mt][j][1] = 0u; }
#pragma unroll
        for (int s = 0; s < 8; s++) {
#pragma unroll
            for (int jp = 0; jp < 4; jp++) {
                unsigned bm[4];
                ldsm4(bm, sptr(Ks + (16 * jp + lrowB) * 136 + s * 16 + lcolB));
#pragma unroll
                for (int mt = 0; mt < 2; mt++) {
                    mma16816_h(ch2[mt][2 * jp], a_q[mt][s], bm[0], bm[1]);
                    mma16816_h(ch2[mt][2 * jp + 1], a_q[mt][s], bm[2], bm[3]);
                }
            }
        }

        // --- softmax per m-tile ---
        unsigned P0[2][8], P1[2][8];
        __half2 alh[2][2];
#pragma unroll
        for (int mt = 0; mt < 2; mt++) {
            __half2 hm0 = *(__half2*)&ch2[mt][0][0], hm1 = *(__half2*)&ch2[mt][0][1];
#pragma unroll
            for (int j = 1; j < 8; j++) {
                hm0 = __hmax2(hm0, *(__half2*)&ch2[mt][j][0]);
                hm1 = __hmax2(hm1, *(__half2*)&ch2[mt][j][1]);
            }
            float rmax0 = fmaxf(__low2float(hm0), __high2float(hm0));
            float rmax1 = fmaxf(__low2float(hm1), __high2float(hm1));
            rmax0 = fmaxf(rmax0, __shfl_xor_sync(0xffffffffu, rmax0, 1));
            rmax0 = fmaxf(rmax0, __shfl_xor_sync(0xffffffffu, rmax0, 2));
            rmax1 = fmaxf(rmax1, __shfl_xor_sync(0xffffffffu, rmax1, 1));
            rmax1 = fmaxf(rmax1, __shfl_xor_sync(0xffffffffu, rmax1, 2));
            float mn0 = fmaxf(mreg[mt][0], rmax0), mn1 = fmaxf(mreg[mt][1], rmax1);
            float al0 = __expf(mreg[mt][0] - mn0), al1 = __expf(mreg[mt][1] - mn1);
            mreg[mt][0] = mn0; mreg[mt][1] = mn1;
            __half2 nb0 = __float2half2_rn(-mn0 * L2E);
            __half2 nb1 = __float2half2_rn(-mn1 * L2E);

            float s0 = 0.f, s1 = 0.f;
#pragma unroll
            for (int j = 0; j < 8; j++) {
                __half2 d0 = __hfma2(*(__half2*)&ch2[mt][j][0], L2E2, nb0);
                __half2 d1 = __hfma2(*(__half2*)&ch2[mt][j][1], L2E2, nb1);
                P0[mt][j] = ex2h2x(*(unsigned*)&d0);
                P1[mt][j] = ex2h2x(*(unsigned*)&d1);
                float2 f0 = __half22float2(*(__half2*)&P0[mt][j]);
                float2 f1 = __half22float2(*(__half2*)&P1[mt][j]);
                s0 += f0.x + f0.y;
                s1 += f1.x + f1.y;
            }
            s0 += __shfl_xor_sync(0xffffffffu, s0, 1);
            s0 += __shfl_xor_sync(0xffffffffu, s0, 2);
            s1 += __shfl_xor_sync(0xffffffffu, s1, 1);
            s1 += __shfl_xor_sync(0xffffffffu, s1, 2);
            lreg[mt][0] = lreg[mt][0] * al0 + s0;
            lreg[mt][1] = lreg[mt][1] * al1 + s1;
            alh[mt][0] = __float2half2_rn(al0);
            alh[mt][1] = __float2half2_rn(al1);
        }
#pragma unroll
        for (int mt = 0; mt < 2; mt++)
#pragma unroll
            for (int j = 0; j < 16; j++) {
                *(__half2*)&oh[mt][j][0] = __hmul2(*(__half2*)&oh[mt][j][0], alh[mt][0]);
                *(__half2*)&oh[mt][j][1] = __hmul2(*(__half2*)&oh[mt][j][1], alh[mt][1]);
            }

        // --- O += P @ G, fp16 accum; each G fragment feeds both m-tiles ---
#pragma unroll
        for (int s = 0; s < 4; s++) {
            unsigned pa[2][4];
#pragma unroll
            for (int mt = 0; mt < 2; mt++) {
                pa[mt][0] = P0[mt][2 * s]; pa[mt][1] = P1[mt][2 * s];
                pa[mt][2] = P0[mt][2 * s + 1]; pa[mt][3] = P1[mt][2 * s + 1];
            }
#pragma unroll
            for (int jp = 0; jp < 8; jp++) {
                unsigned gm[4];
                ldsm4(gm, sptr(Gs + (16 * jp + lrowB) * 72 + s * 16 + lcolB));
#pragma unroll
                for (int mt = 0; mt < 2; mt++) {
                    mma16816_h(oh[mt][2 * jp], pa[mt], gm[0], gm[1]);
                    mma16816_h(oh[mt][2 * jp + 1], pa[mt], gm[2], gm[3]);
                }
            }
        }
    }

    // epilogue
#pragma unroll
    for (int mt = 0; mt < 2; mt++) {
        float inv0 = 1.f / lreg[mt][0], inv1 = 1.f / lreg[mt][1];
        __half2 i0 = __float2half2_rn(inv0), i1 = __float2half2_rn(inv1);
        size_t base = (size_t)b * 4096 + qt * 128 + w * 32 + mt * 16;
#pragma unroll
        for (int j = 0; j < 16; j++) {
            __half2 v0 = __hmul2(*(__half2*)&oh[mt][j][0], i0);
            __half2 v1 = __hmul2(*(__half2*)&oh[mt][j][1], i1);
            *(__half2*)(Y + (base + g) * 128 + j * 8 + 2 * t) = v0;
            *(__half2*)(Y + (base + g + 8) * 128 + j * 8 + 2 * t) = v1;
        }
    }
}

// ---------------- kernel 5: out = elu(bn2(Y)) @ W_z + b_z, *sita + inputs (tensor core) ----------------
#define GZ_SMEM (1024 + 2 * 128 * 136 * 2)
__global__ void __launch_bounds__(256, 2) k_gemm_z_tc(
    const __half* __restrict__ Yh, const __half* __restrict__ WzT,
    const float* __restrict__ bz,
    const float* __restrict__ g2, const float* __restrict__ b2,
    const float* __restrict__ m2, const float* __restrict__ v2,
    const float* __restrict__ sita, const float* __restrict__ resid, float* __restrict__ out)
{
    extern __shared__ char smz[];
    float* bnS = (float*)smz;
    float* bnH = bnS + 128;
    __half* As = (__half*)(bnH + 128);
    __half* Ws = As + 128 * 136;

    int m0 = blockIdx.x * 128;
    int n0 = blockIdx.y * 128;
    int tid = threadIdx.x;
    int w = tid >> 5, l = tid & 31;
    int g = l >> 2, t = l & 3;

    if (tid < 128) {
        float s = g2[tid] * rsqrtf(v2[tid] + EPS);
        bnS[tid] = s;
        bnH[tid] = b2[tid] - m2[tid] * s;
    }
    __syncthreads();

    for (int i = tid; i < 128 * 16; i += 256) {
        int r = i >> 4, c8 = (i & 15) * 8;
        uint4 u = *(const uint4*)(Yh + (size_t)(m0 + r) * 128 + c8);
        __half2* hp = (__half2*)&u;
        uint4 o;
        __half2* op = (__half2*)&o;
#pragma unroll
        for (int k = 0; k < 4; k++) {
            float2 f = __half22float2(hp[k]);
            int c = c8 + 2 * k;
            f.x = elu_f(fmaf(f.x, bnS[c], bnH[c]));
            f.y = elu_f(fmaf(f.y, bnS[c + 1], bnH[c + 1]));
            op[k] = __floats2half2_rn(f.x, f.y);
        }
        *(uint4*)(As + r * 136 + c8) = o;
    }
    for (int i = tid; i < 128 * 16; i += 256) {
        int n = i >> 4, c8 = (i & 15) * 8;
        *(uint4*)(Ws + n * 136 + c8) = *(const uint4*)(WzT + (size_t)(n0 + n) * 128 + c8);
    }
    __syncthreads();

    float c[16][4];
#pragma unroll
    for (int j = 0; j < 16; j++)
#pragma unroll
        for (int q = 0; q < 4; q++) c[j][q] = 0.f;

    int arow = w * 16 + g;
#pragma unroll
    for (int s = 0; s < 8; s++) {
        unsigned a[4];
        a[0] = *(const unsigned*)(As + arow * 136 + s * 16 + 2 * t);
        a[1] = *(const unsigned*)(As + (arow + 8) * 136 + s * 16 + 2 * t);
        a[2] = *(const unsigned*)(As + arow * 136 + s * 16 + 8 + 2 * t);
        a[3] = *(const unsigned*)(As + (arow + 8) * 136 + s * 16 + 8 + 2 * t);
#pragma unroll
        for (int j = 0; j < 16; j++) {
            unsigned bb0 = *(const unsigned*)(Ws + (8 * j + g) * 136 + s * 16 + 2 * t);
            unsigned bb1 = *(const unsigned*)(Ws + (8 * j + g) * 136 + s * 16 + 8 + 2 * t);
            mma16816(c[j], a, bb0, bb1);
        }
    }

    float st = *sita;
    size_t row = (size_t)(m0 + w * 16 + g);
#pragma unroll
    for (int j = 0; j < 16; j++) {
        int col = n0 + j * 8 + 2 * t;
        float bx = bz[col], by = bz[col + 1];
        float2 r0 = *(const float2*)(resid + row * 256 + col);
        float2 r1 = *(const float2*)(resid + (row + 8) * 256 + col);
        float2 v0 = make_float2(fmaf(c[j][0] + bx, st, r0.x), fmaf(c[j][1] + by, st, r0.y));
        float2 v1 = make_float2(fmaf(c[j][2] + bx, st, r1.x), fmaf(c[j][3] + by, st, r1.y));
        *(float2*)(out + row * 256 + col) = v0;
        *(float2*)(out + (row + 8) * 256 + col) = v1;
    }
}

// ---------------- launcher ----------------
extern "C" void kernel_launch(void* const* d_in, const int* in_sizes, int n_in,
                              void* d_out, int out_size)
{
    const float* inputs = (const float*)d_in[0];
    const float* bn1g = (const float*)d_in[1];
    const float* bn1b = (const float*)d_in[2];
    const float* bn1m = (const float*)d_in[3];
    const float* bn1v = (const float*)d_in[4];
    const float* bn2g = (const float*)d_in[5];
    const float* bn2b = (const float*)d_in[6];
    const float* bn2m = (const float*)d_in[7];
    const float* bn2v = (const float*)d_in[8];
    const float* Wg   = (const float*)d_in[9];
    const float* bg   = (const float*)d_in[10];
    const float* Wth  = (const float*)d_in[11];
    const float* bth  = (const float*)d_in[12];
    const float* Wph  = (const float*)d_in[13];
    const float* bph  = (const float*)d_in[14];
    const float* Wz   = (const float*)d_in[15];
    const float* bz   = (const float*)d_in[16];
    const float* sita = (const float*)d_in[17];
    float* out = (float*)d_out;

    __half *X, *theta, *phipool, *gT, *Y, *WT, *WzT;
    cudaGetSymbolAddress((void**)&X, g_X);
    cudaGetSymbolAddress((void**)&theta, g_theta);
    cudaGetSymbolAddress((void**)&phipool, g_phipool);
    cudaGetSymbolAddress((void**)&gT, g_gT);
    cudaGetSymbolAddress((void**)&Y, g_Y);
    cudaGetSymbolAddress((void**)&WT, g_WT);
    cudaGetSymbolAddress((void**)&WzT, g_WzT);

    cudaFuncSetAttribute(k_attn, cudaFuncAttributeMaxDynamicSharedMemorySize, ATTN_SMEM);
    cudaFuncSetAttribute(k_gemm3_tc, cudaFuncAttributeMaxDynamicSharedMemorySize, G3_SMEM);
    cudaFuncSetAttribute(k_gemm_z_tc, cudaFuncAttributeMaxDynamicSharedMemorySize, GZ_SMEM);

    // 0) weight prep
    k_wprep<<<512, 256>>>(Wth, Wg, Wph, Wz, WT, WzT);
    // 1) bn1 + elu (fp16 out)
    k_bn1_elu<<<8192, 256>>>((const float4*)inputs, bn1g, bn1b, bn1m, bn1v, X);
    // 2) theta / g / phi convs (tensor core) with fused pool+transpose for g/phi
    k_gemm3_tc<<<dim3(256, 3), 256, G3_SMEM>>>(X, WT, bth, bg, bph, theta, gT, phipool);
    // 3) flash attention (4 warps x 32 rows)
    k_attn<<<dim3(32, 8), 128, ATTN_SMEM>>>(theta, phipool, gT, Y);
    // 4) bn2+elu -> W_z -> *sita + residual (tensor core)
    k_gemm_z_tc<<<dim3(256, 2), 256, GZ_SMEM>>>(Y, WzT, bz, bn2g, bn2b, bn2m, bn2v, sita, inputs, out);
}

// round 9
// speedup vs baseline: 10.3088x; 1.0330x over previous
#include <cuda_runtime.h>
#include <cuda_fp16.h>
#include <math.h>

#define EPS 1e-3f

// ---------------- scratch (device globals) ----------------
__device__ __half g_X[8 * 4096 * 256];          // bn1+elu(inputs), fp16
__device__ __half g_theta[8 * 4096 * 128];      // Q, fp16
__device__ __half g_phipool[8 * 2048 * 128];    // K [b][key][ch], fp16
__device__ __half g_gT[8 * 128 * 2048];         // V transposed [b][ch][key], fp16
__device__ __half g_Y[8 * 4096 * 128];          // attention out, fp16
__device__ __half g_WT[3 * 128 * 256];          // W_theta/W_g/W_phi transposed [n][k] fp16
__device__ __half g_WzT[256 * 128];             // W_z transposed [n][k] fp16

__device__ __forceinline__ float elu_f(float v) { return v > 0.f ? v : expm1f(v); }

__device__ __forceinline__ unsigned sptr(const void* p) {
    return (unsigned)__cvta_generic_to_shared(p);
}

__device__ __forceinline__ void mma16816(float* c, const unsigned* a, unsigned b0, unsigned b1) {
    asm volatile(
        "mma.sync.aligned.m16n8k16.row.col.f32.f16.f16.f32 "
        "{%0,%1,%2,%3}, {%4,%5,%6,%7}, {%8,%9}, {%0,%1,%2,%3};"
        : "+f"(c[0]), "+f"(c[1]), "+f"(c[2]), "+f"(c[3])
        : "r"(a[0]), "r"(a[1]), "r"(a[2]), "r"(a[3]), "r"(b0), "r"(b1));
}

__device__ __forceinline__ void mma16816_h(unsigned* c, const unsigned* a, unsigned b0, unsigned b1) {
    asm volatile(
        "mma.sync.aligned.m16n8k16.row.col.f16.f16.f16.f16 "
        "{%0,%1}, {%2,%3,%4,%5}, {%6,%7}, {%0,%1};"
        : "+r"(c[0]), "+r"(c[1])
        : "r"(a[0]), "r"(a[1]), "r"(a[2]), "r"(a[3]), "r"(b0), "r"(b1));
}

__device__ __forceinline__ void ldsm4(unsigned* r, unsigned addr) {
    asm volatile("ldmatrix.sync.aligned.m8n8.x4.shared.b16 {%0,%1,%2,%3}, [%4];"
                 : "=r"(r[0]), "=r"(r[1]), "=r"(r[2]), "=r"(r[3]) : "r"(addr));
}

__device__ __forceinline__ unsigned ex2h2x(unsigned x) {
    unsigned r; asm("ex2.approx.f16x2 %0, %1;" : "=r"(r) : "r"(x)); return r;
}

// ---------------- kernel 0: weight prep (fp32 -> fp16 transposed [n][k]) ----------------
__global__ void __launch_bounds__(256) k_wprep(
    const float* __restrict__ Wth, const float* __restrict__ Wg, const float* __restrict__ Wph,
    const float* __restrict__ Wz, __half* __restrict__ WT, __half* __restrict__ WzT)
{
    int idx = blockIdx.x * 256 + threadIdx.x;   // 512*256 = 131072
    if (idx < 98304) {
        int m = idx >> 15;
        int r = idx & 32767;
        int n = r >> 8, k = r & 255;
        const float* W = (m == 0) ? Wth : (m == 1) ? Wg : Wph;
        WT[idx] = __float2half(W[k * 128 + n]);
    } else {
        int r = idx - 98304;
        int n = r >> 7, k = r & 127;
        WzT[r] = __float2half(Wz[k * 256 + n]);
    }
}

// ---------------- kernel 1: x = elu(bn1(inputs)), fp16 out ----------------
__global__ void __launch_bounds__(256) k_bn1_elu(
    const float4* __restrict__ in,
    const float* __restrict__ gamma, const float* __restrict__ beta,
    const float* __restrict__ mean, const float* __restrict__ var,
    __half* __restrict__ X)
{
    int i = blockIdx.x * 256 + threadIdx.x;
    int c = (i & 63) * 4;
    float4 v = in[i];
    float ox = elu_f(fmaf(v.x - mean[c + 0], gamma[c + 0] * rsqrtf(var[c + 0] + EPS), beta[c + 0]));
    float oy = elu_f(fmaf(v.y - mean[c + 1], gamma[c + 1] * rsqrtf(var[c + 1] + EPS), beta[c + 1]));
    float oz = elu_f(fmaf(v.z - mean[c + 2], gamma[c + 2] * rsqrtf(var[c + 2] + EPS), beta[c + 2]));
    float ow = elu_f(fmaf(v.w - mean[c + 3], gamma[c + 3] * rsqrtf(var[c + 3] + EPS), beta[c + 3]));
    __half2 h0 = __floats2half2_rn(ox, oy);
    __half2 h1 = __floats2half2_rn(oz, ow);
    uint2 u; u.x = *(unsigned*)&h0; u.y = *(unsigned*)&h1;
    *(uint2*)(X + (size_t)i * 4) = u;
}

// ---------------- kernel 2: three 1x1 convs, fp16 tensor GEMM + fused pool/transpose ----------------
#define G3_STAGE 18432   // halves per stage: As 128*72 + Ws 128*72
#define G3_SMEM (2 * G3_STAGE * 2)
__global__ void __launch_bounds__(256, 2) k_gemm3_tc(
    const __half* __restrict__ X, const __half* __restrict__ WTall,
    const float* __restrict__ b0p, const float* __restrict__ b1p, const float* __restrict__ b2p,
    __half* __restrict__ theta, __half* __restrict__ gT, __half* __restrict__ phipool)
{
    extern __shared__ __half sm[];
    const __half* WT; const float* bias;
    if (blockIdx.y == 0)      { WT = WTall;         bias = b0p; }
    else if (blockIdx.y == 1) { WT = WTall + 32768; bias = b1p; }
    else                      { WT = WTall + 65536; bias = b2p; }

    int m0 = blockIdx.x * 128;
    int tid = threadIdx.x;
    int w = tid >> 5, l = tid & 31;
    int g = l >> 2, t = l & 3;

    auto issue = [&](int stg, int kc) {
        __half* As = sm + stg * G3_STAGE;
        __half* Ws = As + 9216;
#pragma unroll
        for (int u = 0; u < 4; u++) {
            int i = tid + u * 256;
            int r = i >> 3, c8 = (i & 7) * 8;
            asm volatile("cp.async.cg.shared.global [%0], [%1], 16;\n"
                         :: "r"(sptr(As + r * 72 + c8)), "l"(X + (size_t)(m0 + r) * 256 + kc * 64 + c8));
        }
#pragma unroll
        for (int u = 0; u < 4; u++) {
            int i = tid + u * 256;
            int n = i >> 3, c8 = (i & 7) * 8;
            asm volatile("cp.async.cg.shared.global [%0], [%1], 16;\n"
                         :: "r"(sptr(Ws + n * 72 + c8)), "l"(WT + n * 256 + kc * 64 + c8));
        }
    };

    float c[16][4];
#pragma unroll
    for (int j = 0; j < 16; j++)
#pragma unroll
        for (int q = 0; q < 4; q++) c[j][q] = 0.f;

    issue(0, 0);
    asm volatile("cp.async.commit_group;\n");

    for (int kc = 0; kc < 4; ++kc) {
        int cur = kc & 1;
        asm volatile("cp.async.wait_group 0;\n");
        __syncthreads();
        if (kc < 3) {
            issue(cur ^ 1, kc + 1);
            asm volatile("cp.async.commit_group;\n");
        }
        const __half* As = sm + cur * G3_STAGE;
        const __half* Ws = As + 9216;
        int arow = w * 16 + g;
#pragma unroll
        for (int s = 0; s < 4; s++) {
            unsigned a[4];
            a[0] = *(const unsigned*)(As + arow * 72 + s * 16 + 2 * t);
            a[1] = *(const unsigned*)(As + (arow + 8) * 72 + s * 16 + 2 * t);
            a[2] = *(const unsigned*)(As + arow * 72 + s * 16 + 8 + 2 * t);
            a[3] = *(const unsigned*)(As + (arow + 8) * 72 + s * 16 + 8 + 2 * t);
#pragma unroll
            for (int j = 0; j < 16; j++) {
                unsigned bb0 = *(const unsigned*)(Ws + (8 * j + g) * 72 + s * 16 + 2 * t);
                unsigned bb1 = *(const unsigned*)(Ws + (8 * j + g) * 72 + s * 16 + 8 + 2 * t);
                mma16816(c[j], a, bb0, bb1);
            }
        }
    }

    if (blockIdx.y == 0) {
        int row = m0 + w * 16 + g;
#pragma unroll
        for (int j = 0; j < 16; j++) {
            int col = j * 8 + 2 * t;
            float bx = bias[col], by = bias[col + 1];
            *(__half2*)(theta + (size_t)row * 128 + col) = __floats2half2_rn(c[j][0] + bx, c[j][1] + by);
            *(__half2*)(theta + (size_t)(row + 8) * 128 + col) = __floats2half2_rn(c[j][2] + bx, c[j][3] + by);
        }
        return;
    }

    __syncthreads();
    __half* Cs = sm;                  // [128][136]
    int row = w * 16 + g;
#pragma unroll
    for (int j = 0; j < 16; j++) {
        int col = j * 8 + 2 * t;
        float bx = bias[col], by = bias[col + 1];
        *(__half2*)(Cs + row * 136 + col) = __floats2half2_rn(c[j][0] + bx, c[j][1] + by);
        *(__half2*)(Cs + (row + 8) * 136 + col) = __floats2half2_rn(c[j][2] + bx, c[j][3] + by);
    }
    __syncthreads();

    int bb = m0 >> 12;
    int key0 = (m0 >> 1) & 2047;

    if (blockIdx.y == 2) {
        for (int i = tid; i < 64 * 16; i += 256) {
            int r = i >> 4, c8 = (i & 15) * 8;
            uint4 a4 = *(const uint4*)(Cs + (2 * r) * 136 + c8);
            uint4 b4 = *(const uint4*)(Cs + (2 * r + 1) * 136 + c8);
            __half2* ah = (__half2*)&a4;
            __half2* bh = (__half2*)&b4;
            uint4 o;
            __half2* oh = (__half2*)&o;
#pragma unroll
            for (int k = 0; k < 4; k++) oh[k] = __hmax2(ah[k], bh[k]);
            *(uint4*)(phipool + ((size_t)bb * 2048 + key0 + r) * 128 + c8) = o;
        }
    } else {
        if (tid < 128) {
            int ch = tid;
            __half tmp[64];
#pragma unroll
            for (int k = 0; k < 64; k++)
                tmp[k] = __hmax(Cs[(2 * k) * 136 + ch], Cs[(2 * k + 1) * 136 + ch]);
            float4* dst = (float4*)(gT + ((size_t)(bb * 128 + ch)) * 2048 + key0);
            const float4* src = (const float4*)tmp;
#pragma unroll
            for (int i = 0; i < 8; i++) dst[i] = src[i];
        }
    }
}

// ---------------- kernel 4: flash attention — 8 warps x 32 query rows (Q tile = 256) ----------------
#define STAGE_H 17920
#define KOFF 0
#define GOFF 8704
#define ATTN_SMEM (2 * STAGE_H * 2)

__device__ __forceinline__ void issue_stage(__half* sm, int stg, int kt, int tid,
                                            const __half* Kg, const __half* Gg)
{
    __half* Kd = sm + stg * STAGE_H + KOFF;
    __half* Gd = sm + stg * STAGE_H + GOFF;
    const __half* Kt = Kg + (size_t)kt * 64 * 128;
    const __half* Gt = Gg + kt * 64;
#pragma unroll
    for (int u = 0; u < 4; u++) {
        int i = tid + u * 256;               // [0,1024)
        int r = i >> 4, c8 = (i & 15) * 8;
        asm volatile("cp.async.cg.shared.global [%0], [%1], 16;\n"
                     :: "r"(sptr(Kd + r * 136 + c8)), "l"(Kt + r * 128 + c8));
    }
#pragma unroll
    for (int u = 0; u < 4; u++) {
        int i = tid + u * 256;               // [0,1024)
        int ch = i >> 3, c8 = (i & 7) * 8;
        asm volatile("cp.async.cg.shared.global [%0], [%1], 16;\n"
                     :: "r"(sptr(Gd + ch * 72 + c8)), "l"(Gt + (size_t)ch * 2048 + c8));
    }
}

__global__ void __launch_bounds__(256, 1) k_attn(
    const __half* __restrict__ theta, const __half* __restrict__ phiK,
    const __half* __restrict__ gT, __half* __restrict__ Y)
{
    extern __shared__ __half sm[];

    int b = blockIdx.y, qt = blockIdx.x;
    int tid = threadIdx.x;
    int w = tid >> 5, l = tid & 31;
    int g = l >> 2, t = l & 3;
    const float L2E = 1.4426950408889634f;
    const __half2 L2E2 = __float2half2_rn(L2E);

    int lrowB = (l & 7) + ((l >> 4) << 3);
    int lcolB = ((l >> 3) & 1) * 8;
    int lrowA = (l & 7) + (((l >> 3) & 1) << 3);
    int lcolA = (l >> 4) * 8;

    // --- Q phase: 256-row tile; warp owns rows [w*32, w*32+32) as two m16 tiles ---
    const __half* Qg = theta + ((size_t)b * 4096 + qt * 256) * 128;
    for (int i = tid; i < 256 * 16; i += 256) {
        int r = i >> 4, c8 = (i & 15) * 8;
        *(float4*)(sm + r * 136 + c8) = *(const float4*)(Qg + r * 128 + c8);
    }
    __syncthreads();

    unsigned a_q[2][8][4];
#pragma unroll
    for (int mt = 0; mt < 2; mt++)
#pragma unroll
        for (int s = 0; s < 8; s++)
            ldsm4(a_q[mt][s], sptr(sm + (w * 32 + mt * 16 + lrowA) * 136 + s * 16 + lcolA));
    __syncthreads();

    const __half* Kg = phiK + (size_t)b * 2048 * 128;
    const __half* Gg = gT + (size_t)b * 128 * 2048;

    unsigned oh[2][16][2];
#pragma unroll
    for (int mt = 0; mt < 2; mt++)
#pragma unroll
        for (int j = 0; j < 16; j++) { oh[mt][j][0] = 0u; oh[mt][j][1] = 0u; }
    float mreg[2][2] = {{-1e30f, -1e30f}, {-1e30f, -1e30f}};
    float lreg[2][2] = {{0.f, 0.f}, {0.f, 0.f}};

    issue_stage(sm, 0, 0, tid, Kg, Gg);
    asm volatile("cp.async.commit_group;\n");

    for (int kt = 0; kt < 32; ++kt) {
        int cur = kt & 1;
        asm volatile("cp.async.wait_group 0;\n");
        __syncthreads();
        if (kt < 31) {
            issue_stage(sm, cur ^ 1, kt + 1, tid, Kg, Gg);
            asm volatile("cp.async.commit_group;\n");
        }

        const __half* Ks = sm + cur * STAGE_H + KOFF;
        const __half* Gs = sm + cur * STAGE_H + GOFF;

        // --- S = Q @ K^T, fp16 accum; each K fragment feeds both m-tiles ---
        unsigned ch2[2][8][2];
#pragma unroll
        for (int mt = 0; mt < 2; mt++)
#pragma unroll
            for (int j = 0; j < 8; j++) { ch2[mt][j][0] = 0u; ch2[mt][j][1] = 0u; }
#pragma unroll
        for (int s = 0; s < 8; s++) {
#pragma unroll
            for (int jp = 0; jp < 4; jp++) {
                unsigned bm[4];
                ldsm4(bm, sptr(Ks + (16 * jp + lrowB) * 136 + s * 16 + lcolB));
#pragma unroll
                for (int mt = 0; mt < 2; mt++) {
                    mma16816_h(ch2[mt][2 * jp], a_q[mt][s], bm[0], bm[1]);
                    mma16816_h(ch2[mt][2 * jp + 1], a_q[mt][s], bm[2], bm[3]);
                }
            }
        }

        // --- softmax per m-tile ---
        unsigned P0[2][8], P1[2][8];
        __half2 alh[2][2];
#pragma unroll
        for (int mt = 0; mt < 2; mt++) {
            __half2 hm0 = *(__half2*)&ch2[mt][0][0], hm1 = *(__half2*)&ch2[mt][0][1];
#pragma unroll
            for (int j = 1; j < 8; j++) {
                hm0 = __hmax2(hm0, *(__half2*)&ch2[mt][j][0]);
                hm1 = __hmax2(hm1, *(__half2*)&ch2[mt][j][1]);
            }
            float rmax0 = fmaxf(__low2float(hm0), __high2float(hm0));
            float rmax1 = fmaxf(__low2float(hm1), __high2float(hm1));
            rmax0 = fmaxf(rmax0, __shfl_xor_sync(0xffffffffu, rmax0, 1));
            rmax0 = fmaxf(rmax0, __shfl_xor_sync(0xffffffffu, rmax0, 2));
            rmax1 = fmaxf(rmax1, __shfl_xor_sync(0xffffffffu, rmax1, 1));
            rmax1 = fmaxf(rmax1, __shfl_xor_sync(0xffffffffu, rmax1, 2));
            float mn0 = fmaxf(mreg[mt][0], rmax0), mn1 = fmaxf(mreg[mt][1], rmax1);
            float al0 = __expf(mreg[mt][0] - mn0), al1 = __expf(mreg[mt][1] - mn1);
            mreg[mt][0] = mn0; mreg[mt][1] = mn1;
            __half2 nb0 = __float2half2_rn(-mn0 * L2E);
            __half2 nb1 = __float2half2_rn(-mn1 * L2E);

            float s0 = 0.f, s1 = 0.f;
#pragma unroll
            for (int j = 0; j < 8; j++) {
                __half2 d0 = __hfma2(*(__half2*)&ch2[mt][j][0], L2E2, nb0);
                __half2 d1 = __hfma2(*(__half2*)&ch2[mt][j][1], L2E2, nb1);
                P0[mt][j] = ex2h2x(*(unsigned*)&d0);
                P1[mt][j] = ex2h2x(*(unsigned*)&d1);
                float2 f0 = __half22float2(*(__half2*)&P0[mt][j]);
                float2 f1 = __half22float2(*(__half2*)&P1[mt][j]);
                s0 += f0.x + f0.y;
                s1 += f1.x + f1.y;
            }
            s0 += __shfl_xor_sync(0xffffffffu, s0, 1);
            s0 += __shfl_xor_sync(0xffffffffu, s0, 2);
            s1 += __shfl_xor_sync(0xffffffffu, s1, 1);
            s1 += __shfl_xor_sync(0xffffffffu, s1, 2);
            lreg[mt][0] = lreg[mt][0] * al0 + s0;
            lreg[mt][1] = lreg[mt][1] * al1 + s1;
            alh[mt][0] = __float2half2_rn(al0);
            alh[mt][1] = __float2half2_rn(al1);
        }
#pragma unroll
        for (int mt = 0; mt < 2; mt++)
#pragma unroll
            for (int j = 0; j < 16; j++) {
                *(__half2*)&oh[mt][j][0] = __hmul2(*(__half2*)&oh[mt][j][0], alh[mt][0]);
                *(__half2*)&oh[mt][j][1] = __hmul2(*(__half2*)&oh[mt][j][1], alh[mt][1]);
            }

        // --- O += P @ G, fp16 accum; each G fragment feeds both m-tiles ---
#pragma unroll
        for (int s = 0; s < 4; s++) {
            unsigned pa[2][4];
#pragma unroll
            for (int mt = 0; mt < 2; mt++) {
                pa[mt][0] = P0[mt][2 * s]; pa[mt][1] = P1[mt][2 * s];
                pa[mt][2] = P0[mt][2 * s + 1]; pa[mt][3] = P1[mt][2 * s + 1];
            }
#pragma unroll
            for (int jp = 0; jp < 8; jp++) {
                unsigned gm[4];
                ldsm4(gm, sptr(Gs + (16 * jp + lrowB) * 72 + s * 16 + lcolB));
#pragma unroll
                for (int mt = 0; mt < 2; mt++) {
                    mma16816_h(oh[mt][2 * jp], pa[mt], gm[0], gm[1]);
                    mma16816_h(oh[mt][2 * jp + 1], pa[mt], gm[2], gm[3]);
                }
            }
        }
    }

    // epilogue
#pragma unroll
    for (int mt = 0; mt < 2; mt++) {
        float inv0 = 1.f / lreg[mt][0], inv1 = 1.f / lreg[mt][1];
        __half2 i0 = __float2half2_rn(inv0), i1 = __float2half2_rn(inv1);
        size_t base = (size_t)b * 4096 + qt * 256 + w * 32 + mt * 16;
#pragma unroll
        for (int j = 0; j < 16; j++) {
            __half2 v0 = __hmul2(*(__half2*)&oh[mt][j][0], i0);
            __half2 v1 = __hmul2(*(__half2*)&oh[mt][j][1], i1);
            *(__half2*)(Y + (base + g) * 128 + j * 8 + 2 * t) = v0;
            *(__half2*)(Y + (base + g + 8) * 128 + j * 8 + 2 * t) = v1;
        }
    }
}

// ---------------- kernel 5: out = elu(bn2(Y)) @ W_z + b_z, *sita + inputs (tensor core) ----------------
#define GZ_SMEM (1024 + 2 * 128 * 136 * 2)
__global__ void __launch_bounds__(256, 2) k_gemm_z_tc(
    const __half* __restrict__ Yh, const __half* __restrict__ WzT,
    const float* __restrict__ bz,
    const float* __restrict__ g2, const float* __restrict__ b2,
    const float* __restrict__ m2, const float* __restrict__ v2,
    const float* __restrict__ sita, const float* __restrict__ resid, float* __restrict__ out)
{
    extern __shared__ char smz[];
    float* bnS = (float*)smz;
    float* bnH = bnS + 128;
    __half* As = (__half*)(bnH + 128);
    __half* Ws = As + 128 * 136;

    int m0 = blockIdx.x * 128;
    int n0 = blockIdx.y * 128;
    int tid = threadIdx.x;
    int w = tid >> 5, l = tid & 31;
    int g = l >> 2, t = l & 3;

    if (tid < 128) {
        float s = g2[tid] * rsqrtf(v2[tid] + EPS);
        bnS[tid] = s;
        bnH[tid] = b2[tid] - m2[tid] * s;
    }
    __syncthreads();

    for (int i = tid; i < 128 * 16; i += 256) {
        int r = i >> 4, c8 = (i & 15) * 8;
        uint4 u = *(const uint4*)(Yh + (size_t)(m0 + r) * 128 + c8);
        __half2* hp = (__half2*)&u;
        uint4 o;
        __half2* op = (__half2*)&o;
#pragma unroll
        for (int k = 0; k < 4; k++) {
            float2 f = __half22float2(hp[k]);
            int c = c8 + 2 * k;
            f.x = elu_f(fmaf(f.x, bnS[c], bnH[c]));
            f.y = elu_f(fmaf(f.y, bnS[c + 1], bnH[c + 1]));
            op[k] = __floats2half2_rn(f.x, f.y);
        }
        *(uint4*)(As + r * 136 + c8) = o;
    }
    for (int i = tid; i < 128 * 16; i += 256) {
        int n = i >> 4, c8 = (i & 15) * 8;
        *(uint4*)(Ws + n * 136 + c8) = *(const uint4*)(WzT + (size_t)(n0 + n) * 128 + c8);
    }
    __syncthreads();

    float c[16][4];
#pragma unroll
    for (int j = 0; j < 16; j++)
#pragma unroll
        for (int q = 0; q < 4; q++) c[j][q] = 0.f;

    int arow = w * 16 + g;
#pragma unroll
    for (int s = 0; s < 8; s++) {
        unsigned a[4];
        a[0] = *(const unsigned*)(As + arow * 136 + s * 16 + 2 * t);
        a[1] = *(const unsigned*)(As + (arow + 8) * 136 + s * 16 + 2 * t);
        a[2] = *(const unsigned*)(As + arow * 136 + s * 16 + 8 + 2 * t);
        a[3] = *(const unsigned*)(As + (arow + 8) * 136 + s * 16 + 8 + 2 * t);
#pragma unroll
        for (int j = 0; j < 16; j++) {
            unsigned bb0 = *(const unsigned*)(Ws + (8 * j + g) * 136 + s * 16 + 2 * t);
            unsigned bb1 = *(const unsigned*)(Ws + (8 * j + g) * 136 + s * 16 + 8 + 2 * t);
            mma16816(c[j], a, bb0, bb1);
        }
    }

    float st = *sita;
    size_t row = (size_t)(m0 + w * 16 + g);
#pragma unroll
    for (int j = 0; j < 16; j++) {
        int col = n0 + j * 8 + 2 * t;
        float bx = bz[col], by = bz[col + 1];
        float2 r0 = *(const float2*)(resid + row * 256 + col);
        float2 r1 = *(const float2*)(resid + (row + 8) * 256 + col);
        float2 v0 = make_float2(fmaf(c[j][0] + bx, st, r0.x), fmaf(c[j][1] + by, st, r0.y));
        float2 v1 = make_float2(fmaf(c[j][2] + bx, st, r1.x), fmaf(c[j][3] + by, st, r1.y));
        *(float2*)(out + row * 256 + col) = v0;
        *(float2*)(out + (row + 8) * 256 + col) = v1;
    }
}

// ---------------- launcher ----------------
extern "C" void kernel_launch(void* const* d_in, const int* in_sizes, int n_in,
                              void* d_out, int out_size)
{
    const float* inputs = (const float*)d_in[0];
    const float* bn1g = (const float*)d_in[1];
    const float* bn1b = (const float*)d_in[2];
    const float* bn1m = (const float*)d_in[3];
    const float* bn1v = (const float*)d_in[4];
    const float* bn2g = (const float*)d_in[5];
    const float* bn2b = (const float*)d_in[6];
    const float* bn2m = (const float*)d_in[7];
    const float* bn2v = (const float*)d_in[8];
    const float* Wg   = (const float*)d_in[9];
    const float* bg   = (const float*)d_in[10];
    const float* Wth  = (const float*)d_in[11];
    const float* bth  = (const float*)d_in[12];
    const float* Wph  = (const float*)d_in[13];
    const float* bph  = (const float*)d_in[14];
    const float* Wz   = (const float*)d_in[15];
    const float* bz   = (const float*)d_in[16];
    const float* sita = (const float*)d_in[17];
    float* out = (float*)d_out;

    __half *X, *theta, *phipool, *gT, *Y, *WT, *WzT;
    cudaGetSymbolAddress((void**)&X, g_X);
    cudaGetSymbolAddress((void**)&theta, g_theta);
    cudaGetSymbolAddress((void**)&phipool, g_phipool);
    cudaGetSymbolAddress((void**)&gT, g_gT);
    cudaGetSymbolAddress((void**)&Y, g_Y);
    cudaGetSymbolAddress((void**)&WT, g_WT);
    cudaGetSymbolAddress((void**)&WzT, g_WzT);

    cudaFuncSetAttribute(k_attn, cudaFuncAttributeMaxDynamicSharedMemorySize, ATTN_SMEM);
    cudaFuncSetAttribute(k_gemm3_tc, cudaFuncAttributeMaxDynamicSharedMemorySize, G3_SMEM);
    cudaFuncSetAttribute(k_gemm_z_tc, cudaFuncAttributeMaxDynamicSharedMemorySize, GZ_SMEM);

    // 0) weight prep
    k_wprep<<<512, 256>>>(Wth, Wg, Wph, Wz, WT, WzT);
    // 1) bn1 + elu (fp16 out)
    k_bn1_elu<<<8192, 256>>>((const float4*)inputs, bn1g, bn1b, bn1m, bn1v, X);
    // 2) theta / g / phi convs (tensor core) with fused pool+transpose for g/phi
    k_gemm3_tc<<<dim3(256, 3), 256, G3_SMEM>>>(X, WT, bth, bg, bph, theta, gT, phipool);
    // 3) flash attention (8 warps x 32 rows, Q tile 256)
    k_attn<<<dim3(16, 8), 256, ATTN_SMEM>>>(theta, phipool, gT, Y);
    // 4) bn2+elu -> W_z -> *sita + residual (tensor core)
    k_gemm_z_tc<<<dim3(256, 2), 256, GZ_SMEM>>>(Y, WzT, bz, bn2g, bn2b, bn2m, bn2v, sita, inputs, out);
}